// round 10
// baseline (speedup 1.0000x reference)
#include <cuda_runtime.h>
#include <cuda_bf16.h>
#include <math.h>
#include <stdint.h>

#define HIDDEN 512
#define BATCH  8
#define HW     2304   // 48*48

typedef long long ll;

// ---------------- scratch (static device globals; no allocs allowed) ----------
static __device__ float g_lxT[(size_t)BATCH * HW * HIDDEN];  // locx^T tf32 [B][n][c]
static __device__ float g_gxT[(size_t)BATCH * HW * HIDDEN];  // glox^T tf32
static __device__ float g_q  [(size_t)BATCH * HW * HIDDEN];  // q  split-block bf16 [B][n][c]
static __device__ float g_k  [(size_t)BATCH * HW * HIDDEN];  // k  split-block bf16 [B][m][c]
static __device__ float g_v  [(size_t)BATCH * HIDDEN * HW];  // v  split-block bf16 [B][c][m]
static __device__ float g_ctx[(size_t)BATCH * HW * HIDDEN];  // ctx tf32 [B][n][c]
static __device__ float g_S  [(size_t)BATCH * HW * HW];      // P  split-block bf16 [B][n][m]
static __device__ float g_rsum[(size_t)BATCH * HW];          // softmax row sums
static __device__ float g_wq [HIDDEN * HIDDEN];
static __device__ float g_wk [HIDDEN * HIDDEN];
static __device__ float g_wv [HIDDEN * HIDDEN];
static __device__ float g_wo [HIDDEN * HIDDEN];

// split-block format: row of length K stored as K/32 blocks of 128 bytes;
// block b: bytes [0,64) = bf16 hi of k in [32b,32b+32), bytes [64,128) = bf16 lo.
// Row stride = 4*K bytes (same as fp32).

// ---------------- helpers -----------------------------------------------------
__device__ __forceinline__ float f2tf32f(float f) {
    unsigned u;
    asm("cvt.rna.tf32.f32 %0, %1;" : "=r"(u) : "f"(f));
    return __uint_as_float(u);
}
__device__ __forceinline__ uint32_t smem_u32(const void* p) {
    uint32_t a;
    asm("{ .reg .u64 t; cvta.to.shared.u64 t, %1; cvt.u32.u64 %0, t; }" : "=r"(a) : "l"(p));
    return a;
}
__device__ __forceinline__ void cp16(uint32_t dst, const void* src) {
    asm volatile("cp.async.cg.shared.global [%0], [%1], 16;" :: "r"(dst), "l"(src));
}
__device__ __forceinline__ void ldsm4(uint32_t& r0, uint32_t& r1, uint32_t& r2, uint32_t& r3,
                                      uint32_t addr) {
    asm volatile("ldmatrix.sync.aligned.m8n8.x4.shared.b16 {%0,%1,%2,%3}, [%4];"
                 : "=r"(r0), "=r"(r1), "=r"(r2), "=r"(r3) : "r"(addr));
}
__device__ __forceinline__ void mma_tf32(float& c0, float& c1, float& c2, float& c3,
                                         unsigned a0, unsigned a1, unsigned a2, unsigned a3,
                                         unsigned b0, unsigned b1)
{
    asm volatile(
        "mma.sync.aligned.m16n8k8.row.col.f32.tf32.tf32.f32 "
        "{%0,%1,%2,%3}, {%4,%5,%6,%7}, {%8,%9}, {%0,%1,%2,%3};"
        : "+f"(c0), "+f"(c1), "+f"(c2), "+f"(c3)
        : "r"(a0), "r"(a1), "r"(a2), "r"(a3), "r"(b0), "r"(b1));
}
__device__ __forceinline__ void mma_bf16(float& c0, float& c1, float& c2, float& c3,
                                         unsigned a0, unsigned a1, unsigned a2, unsigned a3,
                                         unsigned b0, unsigned b1)
{
    asm volatile(
        "mma.sync.aligned.m16n8k16.row.col.f32.bf16.bf16.f32 "
        "{%0,%1,%2,%3}, {%4,%5,%6,%7}, {%8,%9}, {%0,%1,%2,%3};"
        : "+f"(c0), "+f"(c1), "+f"(c2), "+f"(c3)
        : "r"(a0), "r"(a1), "r"(a2), "r"(a3), "r"(b0), "r"(b1));
}

// write (a,b) at consecutive cols into split-block row base (char*)
__device__ __forceinline__ void store_sb2(char* rowbase, int col, float a, float b) {
    __nv_bfloat16 h0 = __float2bfloat16(a);
    __nv_bfloat16 l0 = __float2bfloat16(a - __bfloat162float(h0));
    __nv_bfloat16 h1 = __float2bfloat16(b);
    __nv_bfloat16 l1 = __float2bfloat16(b - __bfloat162float(h1));
    __nv_bfloat162 H; H.x = h0; H.y = h1;
    __nv_bfloat162 L; L.x = l0; L.y = l1;
    char* p = rowbase + (col >> 5) * 128 + (col & 31) * 2;
    *(__nv_bfloat162*)p = H;
    *(__nv_bfloat162*)(p + 64) = L;
}

constexpr int TILE   = 128 * 128;       // 16 KB tile (k32 chunk, fp32 OR bf16 hi+lo)
constexpr int STAGE  = 2 * TILE;        // 32 KB
constexpr int NSTAGE = 3;
constexpr int SMEMB  = NSTAGE * STAGE;  // 96 KB

// ---------------- tf32 GEMM (proj / out) --------------------------------------
// D[m][n] = alpha*sum_k A[m][k]*B[n][k] + bias.  A,B fp32 tf32-rounded k-major.
// EPI 0: fp32 out (ROUND: tf32-round). EPI 3: split-block bf16 out (ldc/sC bytes).
// BIAS: 0 none, 1 row, 2 col.
template<int EPI, int BIAS, bool ROUND>
__global__ __launch_bounds__(256, 2)
void gemm_ld(const float* __restrict__ A, int lda, ll sA,
             const float* __restrict__ B, int ldb, ll sB,
             float* __restrict__ C, int ldc, ll sC,
             const float* __restrict__ bias, int K, float alpha)
{
    extern __shared__ __align__(1024) char smem[];
    const uint32_t sb = smem_u32(smem);

    const int bz = blockIdx.z;
    A += (ll)bz * sA;
    B += (ll)bz * sB;

    const int bm = blockIdx.y * 128;
    const int bn = blockIdx.x * 128;
    const int tid  = threadIdx.x;
    const int warp = tid >> 5;
    const int lane = tid & 31;
    const int lr = lane >> 2;
    const int lc = lane & 3;
    const int wm = (warp & 1) * 64;
    const int wn = (warp >> 1) * 32;

    const int row  = tid >> 1;
    const int half = tid & 1;
    const float* gA = A + (size_t)(bm + row) * lda + half * 16;
    const float* gB = B + (size_t)(bn + row) * ldb + half * 16;
    uint32_t dA[4], dB[4];
#pragma unroll
    for (int j = 0; j < 4; j++) {
        int c = half * 4 + j;
        uint32_t off = row * 128 + (((c ^ (row & 7))) << 4);
        dA[j] = sb + off;
        dB[j] = sb + TILE + off;
    }

    const int mi = lane >> 3;
    const int li = lane & 7;
    const uint32_t aoff = (uint32_t)(wm + (mi & 1) * 8 + li) * 128;
    const int     achk = mi >> 1;
    const uint32_t boff = TILE + (uint32_t)(wn + (mi >> 1) * 8 + li) * 128;
    const int     bchk = mi & 1;

    float acc[4][4][4];
#pragma unroll
    for (int i = 0; i < 4; i++)
#pragma unroll
        for (int j = 0; j < 4; j++)
#pragma unroll
            for (int r = 0; r < 4; r++) acc[i][j][r] = 0.f;

    auto ISSUE = [&](int s, int k0) {
        uint32_t st = s * STAGE;
#pragma unroll
        for (int j = 0; j < 4; j++) cp16(dA[j] + st, gA + k0 + j * 4);
#pragma unroll
        for (int j = 0; j < 4; j++) cp16(dB[j] + st, gB + k0 + j * 4);
        asm volatile("cp.async.commit_group;");
    };

    const int nT = K >> 5;
    ISSUE(0, 0);
    ISSUE(1, 32);

    int stage = 0;
    for (int t = 0; t < nT; t++) {
        if (t < nT - 1) asm volatile("cp.async.wait_group 1;");
        else            asm volatile("cp.async.wait_group 0;");
        __syncthreads();

        if (t + 2 < nT) {
            int ps = stage + 2; if (ps >= NSTAGE) ps -= NSTAGE;
            ISSUE(ps, (t + 2) << 5);
        }

        const uint32_t st = sb + stage * STAGE;
#pragma unroll
        for (int ks = 0; ks < 4; ks++) {
            const int c0 = ks * 2;
            uint32_t af[4][4];
            uint32_t bf[4][2];
#pragma unroll
            for (int ti = 0; ti < 4; ti++)
                ldsm4(af[ti][0], af[ti][1], af[ti][2], af[ti][3],
                      st + ti * 2048 + aoff + (((c0 + achk) ^ li) << 4));
#pragma unroll
            for (int tp = 0; tp < 2; tp++)
                ldsm4(bf[2 * tp][0], bf[2 * tp][1], bf[2 * tp + 1][0], bf[2 * tp + 1][1],
                      st + tp * 2048 + boff + (((c0 + bchk) ^ li) << 4));
#pragma unroll
            for (int ti = 0; ti < 4; ti++)
#pragma unroll
                for (int tj = 0; tj < 4; tj++)
                    mma_tf32(acc[ti][tj][0], acc[ti][tj][1], acc[ti][tj][2], acc[ti][tj][3],
                             af[ti][0], af[ti][1], af[ti][2], af[ti][3],
                             bf[tj][0], bf[tj][1]);
        }
        if (++stage == NSTAGE) stage = 0;
    }

    // ---- epilogue ----
    if (EPI == 3) {
        // split-block bf16 out; ldc = row bytes, sC = batch bytes
        char* Cb = (char*)C + (ll)bz * sC;
#pragma unroll
        for (int ti = 0; ti < 4; ti++) {
            int r0 = bm + wm + ti * 16 + lr;
            int r1 = r0 + 8;
            float bv0 = (BIAS == 1) ? bias[r0] : 0.f;
            float bv1 = (BIAS == 1) ? bias[r1] : 0.f;
            char* p0 = Cb + (size_t)r0 * ldc;
            char* p1 = Cb + (size_t)r1 * ldc;
#pragma unroll
            for (int tj = 0; tj < 4; tj++) {
                int col = bn + wn + tj * 8 + lc * 2;
                float c0 = acc[ti][tj][0], c1 = acc[ti][tj][1];
                float c2 = acc[ti][tj][2], c3 = acc[ti][tj][3];
                if (BIAS == 1) { c0 += bv0; c1 += bv0; c2 += bv1; c3 += bv1; }
                if (BIAS == 2) {
                    float b0 = bias[col], b1 = bias[col + 1];
                    c0 += b0; c1 += b1; c2 += b0; c3 += b1;
                }
                store_sb2(p0, col, c0, c1);
                store_sb2(p1, col, c2, c3);
            }
        }
        return;
    }

    C += (ll)bz * sC;
#pragma unroll
    for (int ti = 0; ti < 4; ti++) {
        int r0 = bm + wm + ti * 16 + lr;
        int r1 = r0 + 8;
        float bv0 = (BIAS == 1) ? bias[r0] : 0.f;
        float bv1 = (BIAS == 1) ? bias[r1] : 0.f;
#pragma unroll
        for (int tj = 0; tj < 4; tj++) {
            int col = bn + wn + tj * 8 + lc * 2;
            float c0 = alpha * acc[ti][tj][0];
            float c1 = alpha * acc[ti][tj][1];
            float c2 = alpha * acc[ti][tj][2];
            float c3 = alpha * acc[ti][tj][3];
            if (BIAS == 1) { c0 += bv0; c1 += bv0; c2 += bv1; c3 += bv1; }
            if (BIAS == 2) {
                float b0 = bias[col], b1 = bias[col + 1];
                c0 += b0; c1 += b1; c2 += b0; c3 += b1;
            }
            if (ROUND) {
                c0 = f2tf32f(c0); c1 = f2tf32f(c1);
                c2 = f2tf32f(c2); c3 = f2tf32f(c3);
            }
            float2 o0 = { c0, c1 };
            float2 o1 = { c2, c3 };
            *(float2*)&C[(size_t)r0 * ldc + col] = o0;
            *(float2*)&C[(size_t)r1 * ldc + col] = o1;
        }
    }
}

// ---------------- split-bf16 3-term GEMM (score / PV) -------------------------
// D[m][n] = alpha*sum_k A[m][k]*B[n][k] with A,B in split-block bf16.
// Per k16: acc += Al*Bh + Ah*Bh + Ah*Bl (error ~2^-17, better than tf32).
// EPI 1: out = exp(alpha*acc) -> split-block bf16 + atomic row sums (ldc/sC bytes)
// EPI 2: out = tf32(acc / rsum[row]) -> fp32 linear (ldc elems, sC elems)
template<int EPI>
__global__ __launch_bounds__(256, 2)
void gemm_bf(const char* __restrict__ A, int rowA, ll sA,
             const char* __restrict__ B, int rowB, ll sB,
             float* __restrict__ C, int ldc, ll sC,
             float* __restrict__ rsum, int K, float alpha)
{
    extern __shared__ __align__(1024) char smem[];
    const uint32_t sb = smem_u32(smem);

    const int bz = blockIdx.z;
    A += (ll)bz * sA;
    B += (ll)bz * sB;

    const int bm = blockIdx.y * 128;
    const int bn = blockIdx.x * 128;
    const int tid  = threadIdx.x;
    const int warp = tid >> 5;
    const int lane = tid & 31;
    const int lr = lane >> 2;
    const int lc = lane & 3;
    const int wm = (warp & 1) * 64;
    const int wn = (warp >> 1) * 32;

    const int row  = tid >> 1;
    const int half = tid & 1;
    const char* gA = A + (size_t)(bm + row) * rowA + half * 64;
    const char* gB = B + (size_t)(bn + row) * rowB + half * 64;
    uint32_t dA[4], dB[4];
#pragma unroll
    for (int j = 0; j < 4; j++) {
        int c = half * 4 + j;
        uint32_t off = row * 128 + (((c ^ (row & 7))) << 4);
        dA[j] = sb + off;
        dB[j] = sb + TILE + off;
    }

    const int mi = lane >> 3;
    const int li = lane & 7;
    const uint32_t aoff = (uint32_t)(wm + (mi & 1) * 8 + li) * 128;
    const int     achk = mi >> 1;
    const uint32_t boff = TILE + (uint32_t)(wn + (mi >> 1) * 8 + li) * 128;
    const int     bchk = mi & 1;

    float acc[4][4][4];
#pragma unroll
    for (int i = 0; i < 4; i++)
#pragma unroll
        for (int j = 0; j < 4; j++)
#pragma unroll
            for (int r = 0; r < 4; r++) acc[i][j][r] = 0.f;

    auto ISSUE = [&](int s, int t) {
        uint32_t st = s * STAGE;
        const char* pa = gA + (size_t)t * 128;
        const char* pb = gB + (size_t)t * 128;
#pragma unroll
        for (int j = 0; j < 4; j++) cp16(dA[j] + st, pa + j * 16);
#pragma unroll
        for (int j = 0; j < 4; j++) cp16(dB[j] + st, pb + j * 16);
        asm volatile("cp.async.commit_group;");
    };

    const int nT = K >> 5;
    ISSUE(0, 0);
    ISSUE(1, 1);

    int stage = 0;
    for (int t = 0; t < nT; t++) {
        if (t < nT - 1) asm volatile("cp.async.wait_group 1;");
        else            asm volatile("cp.async.wait_group 0;");
        __syncthreads();

        if (t + 2 < nT) {
            int ps = stage + 2; if (ps >= NSTAGE) ps -= NSTAGE;
            ISSUE(ps, t + 2);
        }

        const uint32_t st = sb + stage * STAGE;
#pragma unroll
        for (int j = 0; j < 2; j++) {        // two k16 steps per chunk
            const int hi0 = j * 2;           // hi chunk base
            const int lo0 = j * 2 + 4;       // lo chunk base
            uint32_t af[4][4];
            uint32_t bf[4][2];
            // term 1: Al * Bh
#pragma unroll
            for (int ti = 0; ti < 4; ti++)
                ldsm4(af[ti][0], af[ti][1], af[ti][2], af[ti][3],
                      st + ti * 2048 + aoff + (((lo0 + achk) ^ li) << 4));
#pragma unroll
            for (int tp = 0; tp < 2; tp++)
                ldsm4(bf[2 * tp][0], bf[2 * tp][1], bf[2 * tp + 1][0], bf[2 * tp + 1][1],
                      st + tp * 2048 + boff + (((hi0 + bchk) ^ li) << 4));
#pragma unroll
            for (int ti = 0; ti < 4; ti++)
#pragma unroll
                for (int tj = 0; tj < 4; tj++)
                    mma_bf16(acc[ti][tj][0], acc[ti][tj][1], acc[ti][tj][2], acc[ti][tj][3],
                             af[ti][0], af[ti][1], af[ti][2], af[ti][3],
                             bf[tj][0], bf[tj][1]);
            // term 2: Ah * Bh  (reload A regs with hi)
#pragma unroll
            for (int ti = 0; ti < 4; ti++)
                ldsm4(af[ti][0], af[ti][1], af[ti][2], af[ti][3],
                      st + ti * 2048 + aoff + (((hi0 + achk) ^ li) << 4));
#pragma unroll
            for (int ti = 0; ti < 4; ti++)
#pragma unroll
                for (int tj = 0; tj < 4; tj++)
                    mma_bf16(acc[ti][tj][0], acc[ti][tj][1], acc[ti][tj][2], acc[ti][tj][3],
                             af[ti][0], af[ti][1], af[ti][2], af[ti][3],
                             bf[tj][0], bf[tj][1]);
            // term 3: Ah * Bl  (reload B regs with lo)
#pragma unroll
            for (int tp = 0; tp < 2; tp++)
                ldsm4(bf[2 * tp][0], bf[2 * tp][1], bf[2 * tp + 1][0], bf[2 * tp + 1][1],
                      st + tp * 2048 + boff + (((lo0 + bchk) ^ li) << 4));
#pragma unroll
            for (int ti = 0; ti < 4; ti++)
#pragma unroll
                for (int tj = 0; tj < 4; tj++)
                    mma_bf16(acc[ti][tj][0], acc[ti][tj][1], acc[ti][tj][2], acc[ti][tj][3],
                             af[ti][0], af[ti][1], af[ti][2], af[ti][3],
                             bf[tj][0], bf[tj][1]);
        }
        if (++stage == NSTAGE) stage = 0;
    }

    // ---- epilogue ----
    if (EPI == 1) {
        // exp(alpha*acc) -> split-block bf16; ldc = row bytes, sC = batch bytes
        char* Cb = (char*)C + (ll)bz * sC;
        float* rs = rsum + (size_t)bz * HW;
#pragma unroll
        for (int ti = 0; ti < 4; ti++) {
            int r0 = bm + wm + ti * 16 + lr;
            int r1 = r0 + 8;
            char* p0 = Cb + (size_t)r0 * ldc;
            char* p1 = Cb + (size_t)r1 * ldc;
            float s0 = 0.f, s1 = 0.f;
#pragma unroll
            for (int tj = 0; tj < 4; tj++) {
                int col = bn + wn + tj * 8 + lc * 2;
                float e0 = __expf(alpha * acc[ti][tj][0]);
                float e1 = __expf(alpha * acc[ti][tj][1]);
                float e2 = __expf(alpha * acc[ti][tj][2]);
                float e3 = __expf(alpha * acc[ti][tj][3]);
                s0 += e0 + e1;
                s1 += e2 + e3;
                store_sb2(p0, col, e0, e1);
                store_sb2(p1, col, e2, e3);
            }
            s0 += __shfl_xor_sync(0xFFFFFFFFu, s0, 1);
            s0 += __shfl_xor_sync(0xFFFFFFFFu, s0, 2);
            s1 += __shfl_xor_sync(0xFFFFFFFFu, s1, 1);
            s1 += __shfl_xor_sync(0xFFFFFFFFu, s1, 2);
            if (lc == 0) {
                atomicAdd(&rs[r0], s0);
                atomicAdd(&rs[r1], s1);
            }
        }
        return;
    }

    // EPI == 2: normalize -> fp32 linear, tf32-rounded
    {
        float* Cf = C + (ll)bz * sC;
        const float* rs = rsum + (size_t)bz * HW;
#pragma unroll
        for (int ti = 0; ti < 4; ti++) {
            int r0 = bm + wm + ti * 16 + lr;
            int r1 = r0 + 8;
            float inv0 = 1.f / rs[r0];
            float inv1 = 1.f / rs[r1];
#pragma unroll
            for (int tj = 0; tj < 4; tj++) {
                int col = bn + wn + tj * 8 + lc * 2;
                float2 o0 = { f2tf32f(acc[ti][tj][0] * inv0), f2tf32f(acc[ti][tj][1] * inv0) };
                float2 o1 = { f2tf32f(acc[ti][tj][2] * inv1), f2tf32f(acc[ti][tj][3] * inv1) };
                *(float2*)&Cf[(size_t)r0 * ldc + col] = o0;
                *(float2*)&Cf[(size_t)r1 * ldc + col] = o1;
            }
        }
    }
}

// ---------------- fused transpose + tf32-round for BOTH inputs ---------------
__global__ __launch_bounds__(256)
void tround_both(const float* __restrict__ Xl, const float* __restrict__ Xg,
                 float* __restrict__ Tl, float* __restrict__ Tg)
{
    __shared__ float tb[32][33];
    const int z = blockIdx.z;
    const int b = (z < BATCH) ? z : z - BATCH;
    const float* x = ((z < BATCH) ? Xl : Xg) + (size_t)b * HIDDEN * HW;
    float* t = ((z < BATCH) ? Tl : Tg) + (size_t)b * HW * HIDDEN;
    const int n0 = blockIdx.x * 32, c0 = blockIdx.y * 32;
    const int tx = threadIdx.x & 31, ty = threadIdx.x >> 5;
#pragma unroll
    for (int j = 0; j < 4; j++)
        tb[ty + j * 8][tx] = x[(size_t)(c0 + ty + j * 8) * HW + n0 + tx];
    __syncthreads();
#pragma unroll
    for (int j = 0; j < 4; j++)
        t[(size_t)(n0 + ty + j * 8) * HIDDEN + c0 + tx] = f2tf32f(tb[tx][ty + j * 8]);
}

// ---------------- fused: tf32-round all 4 weights + zero rsum -----------------
__global__ void roundw_all(const float* __restrict__ W0, float* __restrict__ R0,
                           const float* __restrict__ W1, float* __restrict__ R1,
                           const float* __restrict__ W2, float* __restrict__ R2,
                           const float* __restrict__ W3, float* __restrict__ R3,
                           float* __restrict__ rsum)
{
    const int i = blockIdx.x * 256 + threadIdx.x;
    const int w = blockIdx.y;
    const float* W = (w == 0) ? W0 : (w == 1) ? W1 : (w == 2) ? W2 : W3;
    float*       R = (w == 0) ? R0 : (w == 1) ? R1 : (w == 2) ? R2 : R3;
    R[i] = f2tf32f(W[i]);
    if (w == 0 && i < BATCH * HW) rsum[i] = 0.f;
}

// ---------------- launch -----------------------------------------------------
extern "C" void kernel_launch(void* const* d_in, const int* in_sizes, int n_in,
                              void* d_out, int out_size)
{
    const float* locx = (const float*)d_in[0];
    const float* glox = (const float*)d_in[1];
    const float* Wq = (const float*)d_in[2];  const float* bq = (const float*)d_in[3];
    const float* Wk = (const float*)d_in[4];  const float* bk = (const float*)d_in[5];
    const float* Wv = (const float*)d_in[6];  const float* bv = (const float*)d_in[7];
    const float* Wo = (const float*)d_in[8];  const float* bo = (const float*)d_in[9];
    float* out = (float*)d_out;

#define SYMF(p, s) void* p##_; cudaGetSymbolAddress(&p##_, s); float* p = (float*)p##_
    SYMF(lxT, g_lxT); SYMF(gxT, g_gxT);
    SYMF(q, g_q); SYMF(k, g_k); SYMF(v, g_v); SYMF(ctx, g_ctx); SYMF(S, g_S);
    SYMF(rsum, g_rsum);
    SYMF(wq, g_wq); SYMF(wk, g_wk); SYMF(wv, g_wv); SYMF(wo, g_wo);
#undef SYMF

    cudaFuncSetAttribute(gemm_ld<3, 2, false>, cudaFuncAttributeMaxDynamicSharedMemorySize, SMEMB);
    cudaFuncSetAttribute(gemm_ld<3, 1, false>, cudaFuncAttributeMaxDynamicSharedMemorySize, SMEMB);
    cudaFuncSetAttribute(gemm_ld<0, 1, false>, cudaFuncAttributeMaxDynamicSharedMemorySize, SMEMB);
    cudaFuncSetAttribute(gemm_bf<1>, cudaFuncAttributeMaxDynamicSharedMemorySize, SMEMB);
    cudaFuncSetAttribute(gemm_bf<2>, cudaFuncAttributeMaxDynamicSharedMemorySize, SMEMB);

    const ll sX = (ll)HW * HIDDEN;   // [n][c] per-batch stride (elems)
    const ll sV = (ll)HIDDEN * HW;   // [c][m] per-batch stride (elems)
    const float SCALE = 0.044194173824159216f;   // 1/sqrt(512)
    const int NW = HIDDEN * HIDDEN;

    const int rowQ = HIDDEN * 4;     // split-block row bytes, K=512
    const int rowP = HW * 4;         // split-block row bytes, K=2304
    const ll  sXB = sX * 4;          // batch stride bytes
    const ll  sVB = sV * 4;
    const ll  sSB = (ll)HW * HW * 4;

    dim3 blk(256);
    dim3 gNC(HIDDEN / 128, HW / 128, BATCH);
    dim3 gCN(HW / 128, HIDDEN / 128, BATCH);
    dim3 gNN(HW / 128, HW / 128, BATCH);

    // launch 0: tf32-round all weights + zero row sums
    roundw_all<<<dim3(NW / 256, 4), 256>>>(Wq, wq, Wk, wk, Wv, wv, Wo, wo, rsum);
    // launch 1: transpose-round both inputs
    tround_both<<<dim3(HW / 32, HIDDEN / 32, 2 * BATCH), 256>>>(locx, glox, lxT, gxT);

    // launch 2: q[n,co] (split-block bf16) = lxT . Wq + bq
    gemm_ld<3, 2, false><<<gNC, blk, SMEMB>>>(lxT, HIDDEN, sX, wq, HIDDEN, 0,
                                              q, rowQ, sXB, bq, HIDDEN, 1.f);
    // launch 3: k[m,co] (split-block bf16) = gxT . Wk + bk
    gemm_ld<3, 2, false><<<gNC, blk, SMEMB>>>(gxT, HIDDEN, sX, wk, HIDDEN, 0,
                                              k, rowQ, sXB, bk, HIDDEN, 1.f);
    // launch 4: v[co,m] (split-block bf16) = Wv . gxT + bv
    gemm_ld<3, 1, false><<<gCN, blk, SMEMB>>>(wv, HIDDEN, 0, gxT, HIDDEN, sX,
                                              v, rowP, sVB, bv, HIDDEN, 1.f);
    // launch 5: P[n,m] (split-block bf16) = exp(SCALE * q.k), rsum += rows
    gemm_bf<1><<<gNN, blk, SMEMB>>>((const char*)q, rowQ, sXB,
                                    (const char*)k, rowQ, sXB,
                                    S, rowP, sSB, rsum, HIDDEN, SCALE);
    // launch 6: ctx[n,co] (tf32 fp32) = (P . v) / rsum[n]
    gemm_bf<2><<<gNC, blk, SMEMB>>>((const char*)S, rowP, sSB,
                                    (const char*)v, rowP, sVB,
                                    ctx, HIDDEN, sX, rsum, HW, 1.f);
    // launch 7: out[co,n] = Wo . ctx + bo
    gemm_ld<0, 1, false><<<gCN, blk, SMEMB>>>(wo, HIDDEN, 0, ctx, HIDDEN, sX,
                                              out, HW, sV, bo, HIDDEN, 1.f);
}

// round 11
// speedup vs baseline: 2.1410x; 2.1410x over previous
#include <cuda_runtime.h>
#include <cuda_fp16.h>
#include <math.h>
#include <stdint.h>

#define HIDDEN 512
#define BATCH  8
#define HW     2304   // 48*48

typedef long long ll;

// ---------------- scratch (static device globals; no allocs allowed) ----------
static __device__ __half g_lxT[(size_t)BATCH * HW * HIDDEN];  // locx^T fp16 [B][n][c]
static __device__ __half g_gxT[(size_t)BATCH * HW * HIDDEN];  // glox^T fp16
static __device__ __half g_q  [(size_t)BATCH * HW * HIDDEN];  // q  [B][n][c]
static __device__ __half g_k  [(size_t)BATCH * HW * HIDDEN];  // k  [B][m][c]
static __device__ __half g_v  [(size_t)BATCH * HIDDEN * HW];  // v  [B][c][m]
static __device__ __half g_ctx[(size_t)BATCH * HW * HIDDEN];  // ctx [B][n][c]
static __device__ __half g_S  [(size_t)BATCH * HW * HW];      // P (shifted exp) [B][n][m]
static __device__ float  g_rsum[(size_t)BATCH * HW];          // softmax row sums
static __device__ __half g_wq [HIDDEN * HIDDEN];
static __device__ __half g_wk [HIDDEN * HIDDEN];
static __device__ __half g_wv [HIDDEN * HIDDEN];
static __device__ __half g_wo [HIDDEN * HIDDEN];

// ---------------- helpers -----------------------------------------------------
__device__ __forceinline__ uint32_t smem_u32(const void* p) {
    uint32_t a;
    asm("{ .reg .u64 t; cvta.to.shared.u64 t, %1; cvt.u32.u64 %0, t; }" : "=r"(a) : "l"(p));
    return a;
}
__device__ __forceinline__ void cp16(uint32_t dst, const void* src) {
    asm volatile("cp.async.cg.shared.global [%0], [%1], 16;" :: "r"(dst), "l"(src));
}
__device__ __forceinline__ void ldsm4(uint32_t& r0, uint32_t& r1, uint32_t& r2, uint32_t& r3,
                                      uint32_t addr) {
    asm volatile("ldmatrix.sync.aligned.m8n8.x4.shared.b16 {%0,%1,%2,%3}, [%4];"
                 : "=r"(r0), "=r"(r1), "=r"(r2), "=r"(r3) : "r"(addr));
}
__device__ __forceinline__ void mma_f16(float& c0, float& c1, float& c2, float& c3,
                                        unsigned a0, unsigned a1, unsigned a2, unsigned a3,
                                        unsigned b0, unsigned b1)
{
    asm volatile(
        "mma.sync.aligned.m16n8k16.row.col.f32.f16.f16.f32 "
        "{%0,%1,%2,%3}, {%4,%5,%6,%7}, {%8,%9}, {%0,%1,%2,%3};"
        : "+f"(c0), "+f"(c1), "+f"(c2), "+f"(c3)
        : "r"(a0), "r"(a1), "r"(a2), "r"(a3), "r"(b0), "r"(b1));
}
__device__ __forceinline__ void store_h2(__half* base, size_t idx, float a, float b) {
    __half2 h; h.x = __float2half(a); h.y = __float2half(b);
    *(__half2*)&base[idx] = h;
}

constexpr int TILE   = 128 * 128;       // 16 KB: 128 rows x 128 bytes (k64 fp16)
constexpr int STAGE  = 2 * TILE;        // 32 KB
constexpr int NSTAGE = 3;
constexpr int SMEMB  = NSTAGE * STAGE;  // 96 KB
constexpr float ESHIFT = 4.0f;          // softmax exp shift (cancels in normalize)

// ---------------- fp16 ldmatrix + cp.async GEMM (3-stage) ---------------------
// acc[m][n] = sum_k A[m][k] * B[n][k]; A,B fp16 k-major; byte strides ldaB/ldbB.
// M,N multiples of 128; K multiple of 64. 8 warps, warp tile 64x32.
// Smem: row r at r*128 bytes; 16B chunk c at (c ^ (r&7)).
// EPI 0: fp32 out, + alpha and bias      (BIAS 0 none / 1 row / 2 col)
// EPI 1: fp16 out = exp(alpha*acc - ESHIFT), atomic fp32 row sums
// EPI 2: fp16 out = acc / rsum[row]
// EPI 3: fp16 out = acc + bias           (BIAS 1 row / 2 col)
template<int EPI, int BIAS>
__global__ __launch_bounds__(256, 2)
void gemm_h(const __half* __restrict__ A, int ldaB, ll sAB,
            const __half* __restrict__ B, int ldbB, ll sBB,
            void* __restrict__ Cv, int ldc, ll sC,
            const float* __restrict__ bias, float* __restrict__ rsum,
            int K, float alpha)
{
    extern __shared__ __align__(1024) char smem[];
    const uint32_t sb = smem_u32(smem);

    const int bz = blockIdx.z;
    const char* Ab = (const char*)A + (ll)bz * sAB;
    const char* Bb = (const char*)B + (ll)bz * sBB;

    const int bm = blockIdx.y * 128;
    const int bn = blockIdx.x * 128;
    const int tid  = threadIdx.x;
    const int warp = tid >> 5;
    const int lane = tid & 31;
    const int lr = lane >> 2;
    const int lc = lane & 3;
    const int wm = (warp & 1) * 64;
    const int wn = (warp >> 1) * 32;

    // ---- cp.async source/dest ----
    const int row  = tid >> 1;           // 0..127
    const int half = tid & 1;            // 64B half of the 128B row
    const char* gA = Ab + (size_t)(bm + row) * ldaB + half * 64;
    const char* gB = Bb + (size_t)(bn + row) * ldbB + half * 64;
    uint32_t dA[4], dB[4];
#pragma unroll
    for (int j = 0; j < 4; j++) {
        int c = half * 4 + j;
        uint32_t off = row * 128 + (((c ^ (row & 7))) << 4);
        dA[j] = sb + off;
        dB[j] = sb + TILE + off;
    }

    // ---- ldmatrix lane-address components ----
    const int mi = lane >> 3;            // matrix id 0..3
    const int li = lane & 7;
    // A: a0=(m+0,kc+0) a1=(m+8,kc+0) a2=(m+0,kc+1) a3=(m+8,kc+1)
    const uint32_t aoff = (uint32_t)(wm + (mi & 1) * 8 + li) * 128;
    const int     achk = mi >> 1;
    // B: r0=(n+0,kc+0) r1=(n+0,kc+1) r2=(n+8,kc+0) r3=(n+8,kc+1)
    const uint32_t boff = TILE + (uint32_t)(wn + (mi >> 1) * 8 + li) * 128;
    const int     bchk = mi & 1;

    float acc[4][4][4];
#pragma unroll
    for (int i = 0; i < 4; i++)
#pragma unroll
        for (int j = 0; j < 4; j++)
#pragma unroll
            for (int r = 0; r < 4; r++) acc[i][j][r] = 0.f;

    auto ISSUE = [&](int s, int t) {
        uint32_t st = s * STAGE;
        const char* pa = gA + (size_t)t * 128;
        const char* pb = gB + (size_t)t * 128;
#pragma unroll
        for (int j = 0; j < 4; j++) cp16(dA[j] + st, pa + j * 16);
#pragma unroll
        for (int j = 0; j < 4; j++) cp16(dB[j] + st, pb + j * 16);
        asm volatile("cp.async.commit_group;");
    };

    const int nT = K >> 6;               // k64 chunks; >= 8 for all calls here
    ISSUE(0, 0);
    ISSUE(1, 1);

    int stage = 0;
    for (int t = 0; t < nT; t++) {
        if (t < nT - 1) asm volatile("cp.async.wait_group 1;");
        else            asm volatile("cp.async.wait_group 0;");
        __syncthreads();

        if (t + 2 < nT) {
            int ps = stage + 2; if (ps >= NSTAGE) ps -= NSTAGE;
            ISSUE(ps, t + 2);
        }

        const uint32_t st = sb + stage * STAGE;
#pragma unroll
        for (int kb = 0; kb < 4; kb++) {       // 4 k16 steps per k64 chunk
            const int c0 = kb * 2;
            uint32_t af[4][4];
            uint32_t bf[4][2];
#pragma unroll
            for (int ti = 0; ti < 4; ti++)
                ldsm4(af[ti][0], af[ti][1], af[ti][2], af[ti][3],
                      st + ti * 2048 + aoff + (((c0 + achk) ^ li) << 4));
#pragma unroll
            for (int tp = 0; tp < 2; tp++)
                ldsm4(bf[2 * tp][0], bf[2 * tp][1], bf[2 * tp + 1][0], bf[2 * tp + 1][1],
                      st + tp * 2048 + boff + (((c0 + bchk) ^ li) << 4));
#pragma unroll
            for (int ti = 0; ti < 4; ti++)
#pragma unroll
                for (int tj = 0; tj < 4; tj++)
                    mma_f16(acc[ti][tj][0], acc[ti][tj][1], acc[ti][tj][2], acc[ti][tj][3],
                            af[ti][0], af[ti][1], af[ti][2], af[ti][3],
                            bf[tj][0], bf[tj][1]);
        }
        if (++stage == NSTAGE) stage = 0;
    }

    // ---- epilogue ----
    if (EPI == 0) {
        float* C = (float*)Cv + (ll)bz * sC;
#pragma unroll
        for (int ti = 0; ti < 4; ti++) {
            int r0 = bm + wm + ti * 16 + lr;
            int r1 = r0 + 8;
            float bv0 = (BIAS == 1) ? bias[r0] : 0.f;
            float bv1 = (BIAS == 1) ? bias[r1] : 0.f;
#pragma unroll
            for (int tj = 0; tj < 4; tj++) {
                int col = bn + wn + tj * 8 + lc * 2;
                float c0 = alpha * acc[ti][tj][0];
                float c1 = alpha * acc[ti][tj][1];
                float c2 = alpha * acc[ti][tj][2];
                float c3 = alpha * acc[ti][tj][3];
                if (BIAS == 1) { c0 += bv0; c1 += bv0; c2 += bv1; c3 += bv1; }
                if (BIAS == 2) {
                    float b0 = bias[col], b1 = bias[col + 1];
                    c0 += b0; c1 += b1; c2 += b0; c3 += b1;
                }
                float2 o0 = { c0, c1 };
                float2 o1 = { c2, c3 };
                *(float2*)&C[(size_t)r0 * ldc + col] = o0;
                *(float2*)&C[(size_t)r1 * ldc + col] = o1;
            }
        }
        return;
    }

    if (EPI == 1) {
        __half* C = (__half*)Cv + (ll)bz * sC;
        float* rs = rsum + (size_t)bz * HW;
#pragma unroll
        for (int ti = 0; ti < 4; ti++) {
            int r0 = bm + wm + ti * 16 + lr;
            int r1 = r0 + 8;
            float s0 = 0.f, s1 = 0.f;
#pragma unroll
            for (int tj = 0; tj < 4; tj++) {
                int col = bn + wn + tj * 8 + lc * 2;
                float e0 = __expf(alpha * acc[ti][tj][0] - ESHIFT);
                float e1 = __expf(alpha * acc[ti][tj][1] - ESHIFT);
                float e2 = __expf(alpha * acc[ti][tj][2] - ESHIFT);
                float e3 = __expf(alpha * acc[ti][tj][3] - ESHIFT);
                s0 += e0 + e1;
                s1 += e2 + e3;
                store_h2(C, (size_t)r0 * ldc + col, e0, e1);
                store_h2(C, (size_t)r1 * ldc + col, e2, e3);
            }
            s0 += __shfl_xor_sync(0xFFFFFFFFu, s0, 1);
            s0 += __shfl_xor_sync(0xFFFFFFFFu, s0, 2);
            s1 += __shfl_xor_sync(0xFFFFFFFFu, s1, 1);
            s1 += __shfl_xor_sync(0xFFFFFFFFu, s1, 2);
            if (lc == 0) {
                atomicAdd(&rs[r0], s0);
                atomicAdd(&rs[r1], s1);
            }
        }
        return;
    }

    if (EPI == 2) {
        __half* C = (__half*)Cv + (ll)bz * sC;
        const float* rs = rsum + (size_t)bz * HW;
#pragma unroll
        for (int ti = 0; ti < 4; ti++) {
            int r0 = bm + wm + ti * 16 + lr;
            int r1 = r0 + 8;
            float inv0 = 1.f / rs[r0];
            float inv1 = 1.f / rs[r1];
#pragma unroll
            for (int tj = 0; tj < 4; tj++) {
                int col = bn + wn + tj * 8 + lc * 2;
                store_h2(C, (size_t)r0 * ldc + col, acc[ti][tj][0] * inv0, acc[ti][tj][1] * inv0);
                store_h2(C, (size_t)r1 * ldc + col, acc[ti][tj][2] * inv1, acc[ti][tj][3] * inv1);
            }
        }
        return;
    }

    // EPI == 3: fp16 out + bias
    {
        __half* C = (__half*)Cv + (ll)bz * sC;
#pragma unroll
        for (int ti = 0; ti < 4; ti++) {
            int r0 = bm + wm + ti * 16 + lr;
            int r1 = r0 + 8;
            float bv0 = (BIAS == 1) ? bias[r0] : 0.f;
            float bv1 = (BIAS == 1) ? bias[r1] : 0.f;
#pragma unroll
            for (int tj = 0; tj < 4; tj++) {
                int col = bn + wn + tj * 8 + lc * 2;
                float c0 = acc[ti][tj][0], c1 = acc[ti][tj][1];
                float c2 = acc[ti][tj][2], c3 = acc[ti][tj][3];
                if (BIAS == 1) { c0 += bv0; c1 += bv0; c2 += bv1; c3 += bv1; }
                if (BIAS == 2) {
                    float b0 = bias[col], b1 = bias[col + 1];
                    c0 += b0; c1 += b1; c2 += b0; c3 += b1;
                }
                store_h2(C, (size_t)r0 * ldc + col, c0, c1);
                store_h2(C, (size_t)r1 * ldc + col, c2, c3);
            }
        }
    }
}

// ---------------- fused transpose + fp16 convert for BOTH inputs --------------
__global__ __launch_bounds__(256)
void tround_both(const float* __restrict__ Xl, const float* __restrict__ Xg,
                 __half* __restrict__ Tl, __half* __restrict__ Tg)
{
    __shared__ float tb[32][33];
    const int z = blockIdx.z;
    const int b = (z < BATCH) ? z : z - BATCH;
    const float* x = ((z < BATCH) ? Xl : Xg) + (size_t)b * HIDDEN * HW;
    __half* t = ((z < BATCH) ? Tl : Tg) + (size_t)b * HW * HIDDEN;
    const int n0 = blockIdx.x * 32, c0 = blockIdx.y * 32;
    const int tx = threadIdx.x & 31, ty = threadIdx.x >> 5;
#pragma unroll
    for (int j = 0; j < 4; j++)
        tb[ty + j * 8][tx] = x[(size_t)(c0 + ty + j * 8) * HW + n0 + tx];
    __syncthreads();
#pragma unroll
    for (int j = 0; j < 4; j++)
        t[(size_t)(n0 + ty + j * 8) * HIDDEN + c0 + tx] = __float2half(tb[tx][ty + j * 8]);
}

// ---------------- fused: fp16-convert all 4 weights + zero rsum ---------------
__global__ void roundw_all(const float* __restrict__ W0, __half* __restrict__ R0,
                           const float* __restrict__ W1, __half* __restrict__ R1,
                           const float* __restrict__ W2, __half* __restrict__ R2,
                           const float* __restrict__ W3, __half* __restrict__ R3,
                           float* __restrict__ rsum)
{
    const int i = blockIdx.x * 256 + threadIdx.x;
    const int w = blockIdx.y;
    const float* W = (w == 0) ? W0 : (w == 1) ? W1 : (w == 2) ? W2 : W3;
    __half*      R = (w == 0) ? R0 : (w == 1) ? R1 : (w == 2) ? R2 : R3;
    R[i] = __float2half(W[i]);
    if (w == 0 && i < BATCH * HW) rsum[i] = 0.f;
}

// ---------------- launch -----------------------------------------------------
extern "C" void kernel_launch(void* const* d_in, const int* in_sizes, int n_in,
                              void* d_out, int out_size)
{
    const float* locx = (const float*)d_in[0];
    const float* glox = (const float*)d_in[1];
    const float* Wq = (const float*)d_in[2];  const float* bq = (const float*)d_in[3];
    const float* Wk = (const float*)d_in[4];  const float* bk = (const float*)d_in[5];
    const float* Wv = (const float*)d_in[6];  const float* bv = (const float*)d_in[7];
    const float* Wo = (const float*)d_in[8];  const float* bo = (const float*)d_in[9];
    float* out = (float*)d_out;

#define SYMH(p, s) void* p##_; cudaGetSymbolAddress(&p##_, s); __half* p = (__half*)p##_
    SYMH(lxT, g_lxT); SYMH(gxT, g_gxT);
    SYMH(q, g_q); SYMH(k, g_k); SYMH(v, g_v); SYMH(ctx, g_ctx); SYMH(S, g_S);
    SYMH(wq, g_wq); SYMH(wk, g_wk); SYMH(wv, g_wv); SYMH(wo, g_wo);
#undef SYMH
    void* rsum_; cudaGetSymbolAddress(&rsum_, g_rsum); float* rsum = (float*)rsum_;

    cudaFuncSetAttribute(gemm_h<3, 2>, cudaFuncAttributeMaxDynamicSharedMemorySize, SMEMB);
    cudaFuncSetAttribute(gemm_h<3, 1>, cudaFuncAttributeMaxDynamicSharedMemorySize, SMEMB);
    cudaFuncSetAttribute(gemm_h<1, 0>, cudaFuncAttributeMaxDynamicSharedMemorySize, SMEMB);
    cudaFuncSetAttribute(gemm_h<2, 0>, cudaFuncAttributeMaxDynamicSharedMemorySize, SMEMB);
    cudaFuncSetAttribute(gemm_h<0, 1>, cudaFuncAttributeMaxDynamicSharedMemorySize, SMEMB);

    const ll sX = (ll)HW * HIDDEN;       // [n][c] per-batch stride (elems)
    const ll sV = (ll)HIDDEN * HW;       // [c][m] per-batch stride (elems)
    const ll sS = (ll)HW * HW;
    const float SCALE = 0.044194173824159216f;   // 1/sqrt(512)
    const int NW = HIDDEN * HIDDEN;

    const int rowC = HIDDEN * 2;         // 1024 B: k-major rows of length 512
    const int rowM = HW * 2;             // 4608 B: k-major rows of length 2304
    const ll  sXB = sX * 2;              // byte strides
    const ll  sVB = sV * 2;
    const ll  sSB = sS * 2;

    dim3 blk(256);
    dim3 gNC(HIDDEN / 128, HW / 128, BATCH);
    dim3 gCN(HW / 128, HIDDEN / 128, BATCH);
    dim3 gNN(HW / 128, HW / 128, BATCH);

    // launch 0: fp16 weights + zero row sums
    roundw_all<<<dim3(NW / 256, 4), 256>>>(Wq, wq, Wk, wk, Wv, wv, Wo, wo, rsum);
    // launch 1: transpose + fp16 both inputs
    tround_both<<<dim3(HW / 32, HIDDEN / 32, 2 * BATCH), 256>>>(locx, glox, lxT, gxT);

    // launch 2: q[n,co] = lxT[n,:].Wq[co,:] + bq[co]   (fp16 out, col bias)
    gemm_h<3, 2><<<gNC, blk, SMEMB>>>(lxT, rowC, sXB, wq, rowC, 0,
                                      q, HIDDEN, sX, bq, nullptr, HIDDEN, 1.f);
    // launch 3: k[m,co] = gxT[m,:].Wk[co,:] + bk[co]
    gemm_h<3, 2><<<gNC, blk, SMEMB>>>(gxT, rowC, sXB, wk, rowC, 0,
                                      k, HIDDEN, sX, bk, nullptr, HIDDEN, 1.f);
    // launch 4: v[co,m] = Wv[co,:].gxT[m,:] + bv[co]   (fp16 out, row bias)
    gemm_h<3, 1><<<gCN, blk, SMEMB>>>(wv, rowC, 0, gxT, rowC, sXB,
                                      v, HW, sV, bv, nullptr, HIDDEN, 1.f);
    // launch 5: P[n,m] = exp(SCALE*q.k - ESHIFT) fp16, rsum += rows
    gemm_h<1, 0><<<gNN, blk, SMEMB>>>(q, rowC, sXB, k, rowC, sXB,
                                      S, HW, sS, nullptr, rsum, HIDDEN, SCALE);
    // launch 6: ctx[n,co] = (P[n,:].v[co,:]) / rsum[n]   (fp16 out)
    gemm_h<2, 0><<<gNC, blk, SMEMB>>>(S, rowM, sSB, v, rowM, sVB,
                                      ctx, HIDDEN, sX, nullptr, rsum, HW, 1.f);
    // launch 7: out[co,n] = Wo[co,:].ctx[n,:] + bo[co]   (fp32 out)
    gemm_h<0, 1><<<gCN, blk, SMEMB>>>(wo, rowC, 0, ctx, rowC, sXB,
                                      out, HW, sV, bo, nullptr, HIDDEN, 1.f);
}

// round 12
// speedup vs baseline: 2.1777x; 1.0171x over previous
#include <cuda_runtime.h>
#include <cuda_fp16.h>
#include <math.h>
#include <stdint.h>

#define HIDDEN 512
#define BATCH  8
#define HW     2304   // 48*48

typedef long long ll;

// ---------------- scratch (static device globals; no allocs allowed) ----------
static __device__ __half g_lxT[(size_t)BATCH * HW * HIDDEN];  // locx^T fp16 [B][n][c]
static __device__ __half g_gxT[(size_t)BATCH * HW * HIDDEN];  // glox^T fp16
static __device__ __half g_q  [(size_t)BATCH * HW * HIDDEN];  // q  [B][n][c]
static __device__ __half g_k  [(size_t)BATCH * HW * HIDDEN];  // k  [B][m][c]
static __device__ __half g_v  [(size_t)BATCH * HIDDEN * HW];  // v  [B][c][m]
static __device__ __half g_ctx[(size_t)BATCH * HW * HIDDEN];  // ctx [B][n][c]
static __device__ __half g_S  [(size_t)BATCH * HW * HW];      // P (shifted exp) [B][n][m]
static __device__ float  g_rsum[(size_t)BATCH * HW];          // softmax row sums
static __device__ __half g_wq [HIDDEN * HIDDEN];
static __device__ __half g_wk [HIDDEN * HIDDEN];
static __device__ __half g_wv [HIDDEN * HIDDEN];
static __device__ __half g_wo [HIDDEN * HIDDEN];

// ---------------- helpers -----------------------------------------------------
__device__ __forceinline__ uint32_t smem_u32(const void* p) {
    uint32_t a;
    asm("{ .reg .u64 t; cvta.to.shared.u64 t, %1; cvt.u32.u64 %0, t; }" : "=r"(a) : "l"(p));
    return a;
}
__device__ __forceinline__ void cp16(uint32_t dst, const void* src) {
    asm volatile("cp.async.cg.shared.global [%0], [%1], 16;" :: "r"(dst), "l"(src));
}
__device__ __forceinline__ void ldsm4(uint32_t& r0, uint32_t& r1, uint32_t& r2, uint32_t& r3,
                                      uint32_t addr) {
    asm volatile("ldmatrix.sync.aligned.m8n8.x4.shared.b16 {%0,%1,%2,%3}, [%4];"
                 : "=r"(r0), "=r"(r1), "=r"(r2), "=r"(r3) : "r"(addr));
}
__device__ __forceinline__ void mma_f16(float& c0, float& c1, float& c2, float& c3,
                                        unsigned a0, unsigned a1, unsigned a2, unsigned a3,
                                        unsigned b0, unsigned b1)
{
    asm volatile(
        "mma.sync.aligned.m16n8k16.row.col.f32.f16.f16.f32 "
        "{%0,%1,%2,%3}, {%4,%5,%6,%7}, {%8,%9}, {%0,%1,%2,%3};"
        : "+f"(c0), "+f"(c1), "+f"(c2), "+f"(c3)
        : "r"(a0), "r"(a1), "r"(a2), "r"(a3), "r"(b0), "r"(b1));
}
__device__ __forceinline__ void store_h2(__half* base, size_t idx, float a, float b) {
    __half2 h; h.x = __float2half(a); h.y = __float2half(b);
    *(__half2*)&base[idx] = h;
}

constexpr int TILE   = 128 * 128;       // 16 KB: 128 rows x 128 bytes (k64 fp16)
constexpr int STAGE  = 2 * TILE;        // 32 KB
constexpr int NSTAGE = 3;
constexpr int SMEMB  = NSTAGE * STAGE;  // 96 KB
constexpr float ESHIFT = 4.0f;          // softmax exp shift (cancels in normalize)
constexpr ll SX = (ll)HW * HIDDEN;      // [n][c] per-batch stride (elems)
constexpr ll SV = (ll)HIDDEN * HW;      // [c][m] per-batch stride (elems)
constexpr int ROWC = HIDDEN * 2;        // 1024 B rows (K=512 fp16)

// ---------------- core mainloop as a macro-free inline ------------------------
// Computes acc (4x4x4) for the 128x128 tile at (bm,bn) of A[.][K] x B[.][K]^T.
struct FragCtx {
    uint32_t dA[4], dB[4];
    const char *gA, *gB;
    uint32_t sb, aoff, boff;
    int achk, bchk, li;
};

__device__ __forceinline__ void gemm_core(FragCtx& cx, float acc[4][4][4], int nT)
{
#pragma unroll
    for (int i = 0; i < 4; i++)
#pragma unroll
        for (int j = 0; j < 4; j++)
#pragma unroll
            for (int r = 0; r < 4; r++) acc[i][j][r] = 0.f;

    auto ISSUE = [&](int s, int t) {
        uint32_t st = s * STAGE;
        const char* pa = cx.gA + (size_t)t * 128;
        const char* pb = cx.gB + (size_t)t * 128;
#pragma unroll
        for (int j = 0; j < 4; j++) cp16(cx.dA[j] + st, pa + j * 16);
#pragma unroll
        for (int j = 0; j < 4; j++) cp16(cx.dB[j] + st, pb + j * 16);
        asm volatile("cp.async.commit_group;");
    };

    ISSUE(0, 0);
    ISSUE(1, 1);

    int stage = 0;
    for (int t = 0; t < nT; t++) {
        if (t < nT - 1) asm volatile("cp.async.wait_group 1;");
        else            asm volatile("cp.async.wait_group 0;");
        __syncthreads();

        if (t + 2 < nT) {
            int ps = stage + 2; if (ps >= NSTAGE) ps -= NSTAGE;
            ISSUE(ps, t + 2);
        }

        const uint32_t st = cx.sb + stage * STAGE;
#pragma unroll
        for (int kb = 0; kb < 4; kb++) {       // 4 k16 steps per k64 chunk
            const int c0 = kb * 2;
            uint32_t af[4][4];
            uint32_t bf[4][2];
#pragma unroll
            for (int tp = 0; tp < 2; tp++)
                ldsm4(bf[2 * tp][0], bf[2 * tp][1], bf[2 * tp + 1][0], bf[2 * tp + 1][1],
                      st + tp * 2048 + cx.boff + (((c0 + cx.bchk) ^ cx.li) << 4));
#pragma unroll
            for (int ti = 0; ti < 4; ti++)
                ldsm4(af[ti][0], af[ti][1], af[ti][2], af[ti][3],
                      st + ti * 2048 + cx.aoff + (((c0 + cx.achk) ^ cx.li) << 4));
#pragma unroll
            for (int ti = 0; ti < 4; ti++)
#pragma unroll
                for (int tj = 0; tj < 4; tj++)
                    mma_f16(acc[ti][tj][0], acc[ti][tj][1], acc[ti][tj][2], acc[ti][tj][3],
                            af[ti][0], af[ti][1], af[ti][2], af[ti][3],
                            bf[tj][0], bf[tj][1]);
        }
        if (++stage == NSTAGE) stage = 0;
    }
}

__device__ __forceinline__ void frag_setup(FragCtx& cx, char* smem,
                                           const __half* A, int ldaB,
                                           const __half* B, int ldbB,
                                           int bm, int bn)
{
    cx.sb = smem_u32(smem);
    const int tid  = threadIdx.x;
    const int lane = tid & 31;
    const int warp = tid >> 5;
    const int row  = tid >> 1;
    const int half = tid & 1;
    cx.gA = (const char*)A + (size_t)(bm + row) * ldaB + half * 64;
    cx.gB = (const char*)B + (size_t)(bn + row) * ldbB + half * 64;
#pragma unroll
    for (int j = 0; j < 4; j++) {
        int c = half * 4 + j;
        uint32_t off = row * 128 + (((c ^ (row & 7))) << 4);
        cx.dA[j] = cx.sb + off;
        cx.dB[j] = cx.sb + TILE + off;
    }
    const int mi = lane >> 3;
    cx.li = lane & 7;
    const int wm = (warp & 1) * 64;
    const int wn = (warp >> 1) * 32;
    cx.aoff = (uint32_t)(wm + (mi & 1) * 8 + cx.li) * 128;
    cx.achk = mi >> 1;
    cx.boff = TILE + (uint32_t)(wn + (mi >> 1) * 8 + cx.li) * 128;
    cx.bchk = mi & 1;
}

// ---------------- fused Q/K/V projection kernel -------------------------------
// grid (4, 18, 24): z = op*8 + b; op 0:q 1:k 2:v. All K = 512.
__global__ __launch_bounds__(256, 2)
void qkv_kernel(const float* __restrict__ bq, const float* __restrict__ bk,
                const float* __restrict__ bv)
{
    extern __shared__ __align__(1024) char smem[];
    const int z = blockIdx.z;
    const int op = z >> 3;
    const int b  = z & 7;

    const __half* A;
    const __half* B;
    __half* C;
    const float* bias;
    int bm, bn, ldc, bmode;
    if (op == 0) {
        A = g_lxT + (size_t)b * SX; B = g_wq; C = g_q + (size_t)b * SX;
        bias = bq; bm = blockIdx.y * 128; bn = blockIdx.x * 128; ldc = HIDDEN; bmode = 2;
    } else if (op == 1) {
        A = g_gxT + (size_t)b * SX; B = g_wk; C = g_k + (size_t)b * SX;
        bias = bk; bm = blockIdx.y * 128; bn = blockIdx.x * 128; ldc = HIDDEN; bmode = 2;
    } else {
        A = g_wv; B = g_gxT + (size_t)b * SX; C = g_v + (size_t)b * SV;
        bias = bv; bm = blockIdx.x * 128; bn = blockIdx.y * 128; ldc = HW; bmode = 1;
    }

    FragCtx cx;
    frag_setup(cx, smem, A, ROWC, B, ROWC, bm, bn);
    float acc[4][4][4];
    gemm_core(cx, acc, HIDDEN / 64);

    const int warp = threadIdx.x >> 5;
    const int lane = threadIdx.x & 31;
    const int lr = lane >> 2, lc = lane & 3;
    const int wm = (warp & 1) * 64, wn = (warp >> 1) * 32;
#pragma unroll
    for (int ti = 0; ti < 4; ti++) {
        int r0 = bm + wm + ti * 16 + lr;
        int r1 = r0 + 8;
        float bv0 = (bmode == 1) ? bias[r0] : 0.f;
        float bv1 = (bmode == 1) ? bias[r1] : 0.f;
#pragma unroll
        for (int tj = 0; tj < 4; tj++) {
            int col = bn + wn + tj * 8 + lc * 2;
            float c0 = acc[ti][tj][0], c1 = acc[ti][tj][1];
            float c2 = acc[ti][tj][2], c3 = acc[ti][tj][3];
            if (bmode == 1) { c0 += bv0; c1 += bv0; c2 += bv1; c3 += bv1; }
            else            { float b0 = bias[col], b1 = bias[col + 1];
                              c0 += b0; c1 += b1; c2 += b0; c3 += b1; }
            store_h2(C, (size_t)r0 * ldc + col, c0, c1);
            store_h2(C, (size_t)r1 * ldc + col, c2, c3);
        }
    }
}

// ---------------- score / PV / out kernels ------------------------------------
// EPI 1: score  (A=q, B=k, K=512): P = exp(SCALE*acc - ESHIFT) fp16 + row sums
// EPI 2: PV     (A=P, B=v, K=2304): ctx = acc / rsum[row], fp16
// EPI 0: out    (A=wo, B=ctx, K=512): fp32 + row bias
template<int EPI>
__global__ __launch_bounds__(256, 2)
void gemm_h(const __half* __restrict__ A, int ldaB, ll sAB,
            const __half* __restrict__ B, int ldbB, ll sBB,
            void* __restrict__ Cv, int ldc, ll sC,
            const float* __restrict__ bias, int K, float alpha)
{
    extern __shared__ __align__(1024) char smem[];
    const int bz = blockIdx.z;
    const int bm = blockIdx.y * 128;
    const int bn = blockIdx.x * 128;

    FragCtx cx;
    frag_setup(cx, smem,
               (const __half*)((const char*)A + (ll)bz * sAB), ldaB,
               (const __half*)((const char*)B + (ll)bz * sBB), ldbB,
               bm, bn);
    float acc[4][4][4];
    gemm_core(cx, acc, K / 64);

    const int warp = threadIdx.x >> 5;
    const int lane = threadIdx.x & 31;
    const int lr = lane >> 2, lc = lane & 3;
    const int wm = (warp & 1) * 64, wn = (warp >> 1) * 32;

    if (EPI == 1) {
        __half* C = (__half*)Cv + (ll)bz * sC;
        float* rs = g_rsum + (size_t)bz * HW;
#pragma unroll
        for (int ti = 0; ti < 4; ti++) {
            int r0 = bm + wm + ti * 16 + lr;
            int r1 = r0 + 8;
            float s0 = 0.f, s1 = 0.f;
#pragma unroll
            for (int tj = 0; tj < 4; tj++) {
                int col = bn + wn + tj * 8 + lc * 2;
                float e0 = __expf(alpha * acc[ti][tj][0] - ESHIFT);
                float e1 = __expf(alpha * acc[ti][tj][1] - ESHIFT);
                float e2 = __expf(alpha * acc[ti][tj][2] - ESHIFT);
                float e3 = __expf(alpha * acc[ti][tj][3] - ESHIFT);
                s0 += e0 + e1;
                s1 += e2 + e3;
                store_h2(C, (size_t)r0 * ldc + col, e0, e1);
                store_h2(C, (size_t)r1 * ldc + col, e2, e3);
            }
            s0 += __shfl_xor_sync(0xFFFFFFFFu, s0, 1);
            s0 += __shfl_xor_sync(0xFFFFFFFFu, s0, 2);
            s1 += __shfl_xor_sync(0xFFFFFFFFu, s1, 1);
            s1 += __shfl_xor_sync(0xFFFFFFFFu, s1, 2);
            if (lc == 0) {
                atomicAdd(&rs[r0], s0);
                atomicAdd(&rs[r1], s1);
            }
        }
        return;
    }

    if (EPI == 2) {
        __half* C = (__half*)Cv + (ll)bz * sC;
        const float* rs = g_rsum + (size_t)bz * HW;
#pragma unroll
        for (int ti = 0; ti < 4; ti++) {
            int r0 = bm + wm + ti * 16 + lr;
            int r1 = r0 + 8;
            float inv0 = 1.f / rs[r0];
            float inv1 = 1.f / rs[r1];
#pragma unroll
            for (int tj = 0; tj < 4; tj++) {
                int col = bn + wn + tj * 8 + lc * 2;
                store_h2(C, (size_t)r0 * ldc + col, acc[ti][tj][0] * inv0, acc[ti][tj][1] * inv0);
                store_h2(C, (size_t)r1 * ldc + col, acc[ti][tj][2] * inv1, acc[ti][tj][3] * inv1);
            }
        }
        return;
    }

    // EPI == 0: fp32 out + row bias
    {
        float* C = (float*)Cv + (ll)bz * sC;
#pragma unroll
        for (int ti = 0; ti < 4; ti++) {
            int r0 = bm + wm + ti * 16 + lr;
            int r1 = r0 + 8;
            float bv0 = bias[r0];
            float bv1 = bias[r1];
#pragma unroll
            for (int tj = 0; tj < 4; tj++) {
                int col = bn + wn + tj * 8 + lc * 2;
                float2 o0 = { acc[ti][tj][0] + bv0, acc[ti][tj][1] + bv0 };
                float2 o1 = { acc[ti][tj][2] + bv1, acc[ti][tj][3] + bv1 };
                *(float2*)&C[(size_t)r0 * ldc + col] = o0;
                *(float2*)&C[(size_t)r1 * ldc + col] = o1;
            }
        }
    }
}

// ---------------- fused prep: transpose-convert inputs + convert weights ------
// grid (72, 16, 20): z<16 -> input slice (z<8: locx b=z; else glox b=z-8)
//                    z>=16 -> weight w=z-16 (flat convert); z==16 zeroes rsum
__global__ __launch_bounds__(256)
void prep_all(const float* __restrict__ Xl, const float* __restrict__ Xg,
              const float* __restrict__ W0, const float* __restrict__ W1,
              const float* __restrict__ W2, const float* __restrict__ W3)
{
    const int z = blockIdx.z;
    if (z >= 16) {
        const int w = z - 16;
        const float* W = (w == 0) ? W0 : (w == 1) ? W1 : (w == 2) ? W2 : W3;
        __half* R = (w == 0) ? g_wq : (w == 1) ? g_wk : (w == 2) ? g_wv : g_wo;
        const int i = (blockIdx.y * 72 + blockIdx.x) * 256 + threadIdx.x;
        if (i < HIDDEN * HIDDEN) R[i] = __float2half(W[i]);
        if (w == 0 && i < BATCH * HW) g_rsum[i] = 0.f;
        return;
    }
    __shared__ float tb[32][33];
    const int b = z & 7;
    const float* x = ((z < 8) ? Xl : Xg) + (size_t)b * HIDDEN * HW;
    __half* t = ((z < 8) ? g_lxT : g_gxT) + (size_t)b * HW * HIDDEN;
    const int n0 = blockIdx.x * 32, c0 = blockIdx.y * 32;
    const int tx = threadIdx.x & 31, ty = threadIdx.x >> 5;
#pragma unroll
    for (int j = 0; j < 4; j++)
        tb[ty + j * 8][tx] = x[(size_t)(c0 + ty + j * 8) * HW + n0 + tx];
    __syncthreads();
#pragma unroll
    for (int j = 0; j < 4; j++)
        t[(size_t)(n0 + ty + j * 8) * HIDDEN + c0 + tx] = __float2half(tb[tx][ty + j * 8]);
}

// ---------------- launch -----------------------------------------------------
extern "C" void kernel_launch(void* const* d_in, const int* in_sizes, int n_in,
                              void* d_out, int out_size)
{
    const float* locx = (const float*)d_in[0];
    const float* glox = (const float*)d_in[1];
    const float* Wq = (const float*)d_in[2];  const float* bq = (const float*)d_in[3];
    const float* Wk = (const float*)d_in[4];  const float* bk = (const float*)d_in[5];
    const float* Wv = (const float*)d_in[6];  const float* bv = (const float*)d_in[7];
    const float* Wo = (const float*)d_in[8];  const float* bo = (const float*)d_in[9];
    float* out = (float*)d_out;

    __half *q, *k, *v, *ctx, *S, *wo;
    { void* p; cudaGetSymbolAddress(&p, g_q);   q   = (__half*)p; }
    { void* p; cudaGetSymbolAddress(&p, g_k);   k   = (__half*)p; }
    { void* p; cudaGetSymbolAddress(&p, g_v);   v   = (__half*)p; }
    { void* p; cudaGetSymbolAddress(&p, g_ctx); ctx = (__half*)p; }
    { void* p; cudaGetSymbolAddress(&p, g_S);   S   = (__half*)p; }
    { void* p; cudaGetSymbolAddress(&p, g_wo);  wo  = (__half*)p; }

    cudaFuncSetAttribute(qkv_kernel, cudaFuncAttributeMaxDynamicSharedMemorySize, SMEMB);
    cudaFuncSetAttribute(gemm_h<0>, cudaFuncAttributeMaxDynamicSharedMemorySize, SMEMB);
    cudaFuncSetAttribute(gemm_h<1>, cudaFuncAttributeMaxDynamicSharedMemorySize, SMEMB);
    cudaFuncSetAttribute(gemm_h<2>, cudaFuncAttributeMaxDynamicSharedMemorySize, SMEMB);

    const ll sS = (ll)HW * HW;
    const float SCALE = 0.044194173824159216f;   // 1/sqrt(512)
    const int rowM = HW * 2;                     // 4608 B rows (K=2304 fp16)

    dim3 blk(256);

    // launch 0: fused prep (transpose+convert inputs, convert weights, zero rsum)
    prep_all<<<dim3(72, 16, 20), blk>>>(locx, glox, Wq, Wk, Wv, Wo);
    // launch 1: fused q/k/v projections
    qkv_kernel<<<dim3(4, 18, 24), blk, SMEMB>>>(bq, bk, bv);
    // launch 2: P[n,m] = exp(SCALE*q.k - ESHIFT) fp16, rsum += rows
    gemm_h<1><<<dim3(18, 18, 8), blk, SMEMB>>>(q, ROWC, SX * 2, k, ROWC, SX * 2,
                                               S, HW, sS, nullptr, HIDDEN, SCALE);
    // launch 3: ctx[n,co] = (P[n,:].v[co,:]) / rsum[n]  (fp16)
    gemm_h<2><<<dim3(4, 18, 8), blk, SMEMB>>>(S, rowM, sS * 2, v, rowM, SV * 2,
                                              ctx, HIDDEN, SX, nullptr, HW, 1.f);
    // launch 4: out[co,n] = wo[co,:].ctx[n,:] + bo[co]  (fp32)
    gemm_h<0><<<dim3(18, 4, 8), blk, SMEMB>>>(wo, ROWC, 0, ctx, ROWC, SX * 2,
                                              out, HW, SV, bo, HIDDEN, 1.f);
}

// round 14
// speedup vs baseline: 2.1827x; 1.0023x over previous
#include <cuda_runtime.h>
#include <cuda_fp16.h>
#include <math.h>
#include <stdint.h>

#define HIDDEN 512
#define BATCH  8
#define HW     2304   // 48*48

typedef long long ll;

// ---------------- scratch (static device globals; no allocs allowed) ----------
static __device__ __half g_lxT[(size_t)BATCH * HW * HIDDEN];  // locx^T fp16 [B][n][c]
static __device__ __half g_gxT[(size_t)BATCH * HW * HIDDEN];  // glox^T fp16
static __device__ __half g_q  [(size_t)BATCH * HW * HIDDEN];  // q  [B][n][c]
static __device__ __half g_k  [(size_t)BATCH * HW * HIDDEN];  // k  [B][m][c]
static __device__ __half g_v  [(size_t)BATCH * HIDDEN * HW];  // v  [B][c][m]
static __device__ __half g_ctx[(size_t)BATCH * HW * HIDDEN];  // ctx [B][n][c]
static __device__ __half g_S  [(size_t)BATCH * HW * HW];      // P (shifted exp) [B][n][m]
static __device__ float  g_rsum[(size_t)BATCH * HW];          // softmax row sums
static __device__ __half g_wq [HIDDEN * HIDDEN];
static __device__ __half g_wk [HIDDEN * HIDDEN];
static __device__ __half g_wv [HIDDEN * HIDDEN];
static __device__ __half g_wo [HIDDEN * HIDDEN];

// ---------------- helpers -----------------------------------------------------
__device__ __forceinline__ uint32_t smem_u32(const void* p) {
    uint32_t a;
    asm("{ .reg .u64 t; cvta.to.shared.u64 t, %1; cvt.u32.u64 %0, t; }" : "=r"(a) : "l"(p));
    return a;
}
__device__ __forceinline__ void cp16(uint32_t dst, const void* src) {
    asm volatile("cp.async.cg.shared.global [%0], [%1], 16;" :: "r"(dst), "l"(src));
}
__device__ __forceinline__ void ldsm4(uint32_t& r0, uint32_t& r1, uint32_t& r2, uint32_t& r3,
                                      uint32_t addr) {
    asm volatile("ldmatrix.sync.aligned.m8n8.x4.shared.b16 {%0,%1,%2,%3}, [%4];"
                 : "=r"(r0), "=r"(r1), "=r"(r2), "=r"(r3) : "r"(addr));
}
__device__ __forceinline__ void mma_f16(float& c0, float& c1, float& c2, float& c3,
                                        unsigned a0, unsigned a1, unsigned a2, unsigned a3,
                                        unsigned b0, unsigned b1)
{
    asm("mma.sync.aligned.m16n8k16.row.col.f32.f16.f16.f32 "
        "{%0,%1,%2,%3}, {%4,%5,%6,%7}, {%8,%9}, {%0,%1,%2,%3};"
        : "+f"(c0), "+f"(c1), "+f"(c2), "+f"(c3)
        : "r"(a0), "r"(a1), "r"(a2), "r"(a3), "r"(b0), "r"(b1));
}
__device__ __forceinline__ void store_h2(__half* base, size_t idx, float a, float b) {
    __half2 h; h.x = __float2half(a); h.y = __float2half(b);
    *(__half2*)&base[idx] = h;
}

constexpr int TILE   = 128 * 128;       // 16 KB: 128 rows x 128 bytes (k64 fp16)
constexpr int STAGE  = 2 * TILE;        // 32 KB
constexpr int NSTAGE = 3;
constexpr int SMEMB  = NSTAGE * STAGE;  // 96 KB
constexpr float ESHIFT = 4.0f;          // softmax exp shift (cancels in normalize)
constexpr ll SX = (ll)HW * HIDDEN;      // [n][c] per-batch stride (elems)
constexpr ll SV = (ll)HIDDEN * HW;      // [c][m] per-batch stride (elems)
constexpr int ROWC = HIDDEN * 2;        // 1024 B rows (K=512 fp16)

// ---------------- core mainloop ------------------------------------------------
struct FragCtx {
    uint32_t dA[4], dB[4];
    const char *gA, *gB;
    uint32_t sb, aoff, boff;
    int achk, bchk, li, wst;
};

__device__ __forceinline__ void gemm_core(FragCtx& cx, float acc[4][4][4], int nT)
{
#pragma unroll
    for (int i = 0; i < 4; i++)
#pragma unroll
        for (int j = 0; j < 4; j++)
#pragma unroll
            for (int r = 0; r < 4; r++) acc[i][j][r] = 0.f;

    auto ISSUE = [&](int s, int t) {
        uint32_t st = s * STAGE;
        const char* pa = cx.gA + (size_t)t * 128;
        const char* pb = cx.gB + (size_t)t * 128;
#pragma unroll
        for (int j = 0; j < 4; j++) cp16(cx.dA[j] + st, pa + j * 16);
#pragma unroll
        for (int j = 0; j < 4; j++) cp16(cx.dB[j] + st, pb + j * 16);
        asm volatile("cp.async.commit_group;");
    };

    ISSUE(0, 0);
    ISSUE(1, 1);

    int stage = 0;
    for (int t = 0; t < nT; t++) {
        if (t < nT - 1) asm volatile("cp.async.wait_group 1;");
        else            asm volatile("cp.async.wait_group 0;");
        __syncthreads();

        if (t + 2 < nT) {
            int ps = stage + 2; if (ps >= NSTAGE) ps -= NSTAGE;
            ISSUE(ps, t + 2);
        }

        const uint32_t st = cx.sb + stage * STAGE;
        // Phase-staggered k-steps: warp w starts at kb = w&3. At any moment
        // warps are in different LDSM/MMA phases -> crossbar and tensor pipes
        // are fed continuously instead of in alternating bursts.
#pragma unroll
        for (int kb0 = 0; kb0 < 4; kb0++) {
            const int kb = (kb0 + cx.wst) & 3;
            const int c0 = kb * 2;
            uint32_t af[4][4];
            uint32_t bf[4][2];
#pragma unroll
            for (int tp = 0; tp < 2; tp++)
                ldsm4(bf[2 * tp][0], bf[2 * tp][1], bf[2 * tp + 1][0], bf[2 * tp + 1][1],
                      st + tp * 2048 + cx.boff + (((c0 + cx.bchk) ^ cx.li) << 4));
#pragma unroll
            for (int ti = 0; ti < 4; ti++)
                ldsm4(af[ti][0], af[ti][1], af[ti][2], af[ti][3],
                      st + ti * 2048 + cx.aoff + (((c0 + cx.achk) ^ cx.li) << 4));
#pragma unroll
            for (int ti = 0; ti < 4; ti++)
#pragma unroll
                for (int tj = 0; tj < 4; tj++)
                    mma_f16(acc[ti][tj][0], acc[ti][tj][1], acc[ti][tj][2], acc[ti][tj][3],
                            af[ti][0], af[ti][1], af[ti][2], af[ti][3],
                            bf[tj][0], bf[tj][1]);
        }
        if (++stage == NSTAGE) stage = 0;
    }
}

__device__ __forceinline__ void frag_setup(FragCtx& cx, char* smem,
                                           const __half* A, int ldaB,
                                           const __half* B, int ldbB,
                                           int bm, int bn)
{
    cx.sb = smem_u32(smem);
    const int tid  = threadIdx.x;
    const int lane = tid & 31;
    const int warp = tid >> 5;
    const int row  = tid >> 1;
    const int half = tid & 1;
    cx.gA = (const char*)A + (size_t)(bm + row) * ldaB + half * 64;
    cx.gB = (const char*)B + (size_t)(bn + row) * ldbB + half * 64;
#pragma unroll
    for (int j = 0; j < 4; j++) {
        int c = half * 4 + j;
        uint32_t off = row * 128 + (((c ^ (row & 7))) << 4);
        cx.dA[j] = cx.sb + off;
        cx.dB[j] = cx.sb + TILE + off;
    }
    const int mi = lane >> 3;
    cx.li = lane & 7;
    const int wm = (warp & 1) * 64;
    const int wn = (warp >> 1) * 32;
    cx.aoff = (uint32_t)(wm + (mi & 1) * 8 + cx.li) * 128;
    cx.achk = mi >> 1;
    cx.boff = TILE + (uint32_t)(wn + (mi >> 1) * 8 + cx.li) * 128;
    cx.bchk = mi & 1;
    cx.wst  = warp & 3;
}

// ---------------- fused Q/K/V projection kernel -------------------------------
// grid (4, 18, 24): z = op*8 + b; op 0:q 1:k 2:v. All K = 512.
__global__ __launch_bounds__(256, 2)
void qkv_kernel(const float* __restrict__ bq, const float* __restrict__ bk,
                const float* __restrict__ bv)
{
    extern __shared__ __align__(1024) char smem[];
    const int z = blockIdx.z;
    const int op = z >> 3;
    const int b  = z & 7;

    const __half* A;
    const __half* B;
    __half* C;
    const float* bias;
    int bm, bn, ldc, bmode;
    if (op == 0) {
        A = g_lxT + (size_t)b * SX; B = g_wq; C = g_q + (size_t)b * SX;
        bias = bq; bm = blockIdx.y * 128; bn = blockIdx.x * 128; ldc = HIDDEN; bmode = 2;
    } else if (op == 1) {
        A = g_gxT + (size_t)b * SX; B = g_wk; C = g_k + (size_t)b * SX;
        bias = bk; bm = blockIdx.y * 128; bn = blockIdx.x * 128; ldc = HIDDEN; bmode = 2;
    } else {
        A = g_wv; B = g_gxT + (size_t)b * SX; C = g_v + (size_t)b * SV;
        bias = bv; bm = blockIdx.x * 128; bn = blockIdx.y * 128; ldc = HW; bmode = 1;
    }

    FragCtx cx;
    frag_setup(cx, smem, A, ROWC, B, ROWC, bm, bn);
    float acc[4][4][4];
    gemm_core(cx, acc, HIDDEN / 64);

    const int warp = threadIdx.x >> 5;
    const int lane = threadIdx.x & 31;
    const int lr = lane >> 2, lc = lane & 3;
    const int wm = (warp & 1) * 64, wn = (warp >> 1) * 32;
#pragma unroll
    for (int ti = 0; ti < 4; ti++) {
        int r0 = bm + wm + ti * 16 + lr;
        int r1 = r0 + 8;
        float bv0 = (bmode == 1) ? bias[r0] : 0.f;
        float bv1 = (bmode == 1) ? bias[r1] : 0.f;
#pragma unroll
        for (int tj = 0; tj < 4; tj++) {
            int col = bn + wn + tj * 8 + lc * 2;
            float c0 = acc[ti][tj][0], c1 = acc[ti][tj][1];
            float c2 = acc[ti][tj][2], c3 = acc[ti][tj][3];
            if (bmode == 1) { c0 += bv0; c1 += bv0; c2 += bv1; c3 += bv1; }
            else            { float b0 = bias[col], b1 = bias[col + 1];
                              c0 += b0; c1 += b1; c2 += b0; c3 += b1; }
            store_h2(C, (size_t)r0 * ldc + col, c0, c1);
            store_h2(C, (size_t)r1 * ldc + col, c2, c3);
        }
    }
}

// ---------------- score / PV / out kernels ------------------------------------
// EPI 1: score  (A=q, B=k, K=512): P = exp(SCALE*acc - ESHIFT) fp16 + row sums
// EPI 2: PV     (A=P, B=v, K=2304): ctx = acc / rsum[row], fp16
// EPI 0: out    (A=wo, B=ctx, K=512): fp32 + row bias
template<int EPI>
__global__ __launch_bounds__(256, 2)
void gemm_h(const __half* __restrict__ A, int ldaB, ll sAB,
            const __half* __restrict__ B, int ldbB, ll sBB,
            void* __restrict__ Cv, int ldc, ll sC,
            const float* __restrict__ bias, int K, float alpha)
{
    extern __shared__ __align__(1024) char smem[];
    const int bz = blockIdx.z;
    const int bm = blockIdx.y * 128;
    const int bn = blockIdx.x * 128;

    FragCtx cx;
    frag_setup(cx, smem,
               (const __half*)((const char*)A + (ll)bz * sAB), ldaB,
               (const __half*)((const char*)B + (ll)bz * sBB), ldbB,
               bm, bn);
    float acc[4][4][4];
    gemm_core(cx, acc, K / 64);

    const int warp = threadIdx.x >> 5;
    const int lane = threadIdx.x & 31;
    const int lr = lane >> 2, lc = lane & 3;
    const int wm = (warp & 1) * 64, wn = (warp >> 1) * 32;

    if (EPI == 1) {
        __half* C = (__half*)Cv + (ll)bz * sC;
        float* rs = g_rsum + (size_t)bz * HW;
#pragma unroll
        for (int ti = 0; ti < 4; ti++) {
            int r0 = bm + wm + ti * 16 + lr;
            int r1 = r0 + 8;
            float s0 = 0.f, s1 = 0.f;
#pragma unroll
            for (int tj = 0; tj < 4; tj++) {
                int col = bn + wn + tj * 8 + lc * 2;
                float e0 = __expf(alpha * acc[ti][tj][0] - ESHIFT);
                float e1 = __expf(alpha * acc[ti][tj][1] - ESHIFT);
                float e2 = __expf(alpha * acc[ti][tj][2] - ESHIFT);
                float e3 = __expf(alpha * acc[ti][tj][3] - ESHIFT);
                s0 += e0 + e1;
                s1 += e2 + e3;
                store_h2(C, (size_t)r0 * ldc + col, e0, e1);
                store_h2(C, (size_t)r1 * ldc + col, e2, e3);
            }
            s0 += __shfl_xor_sync(0xFFFFFFFFu, s0, 1);
            s0 += __shfl_xor_sync(0xFFFFFFFFu, s0, 2);
            s1 += __shfl_xor_sync(0xFFFFFFFFu, s1, 1);
            s1 += __shfl_xor_sync(0xFFFFFFFFu, s1, 2);
            if (lc == 0) {
                atomicAdd(&rs[r0], s0);
                atomicAdd(&rs[r1], s1);
            }
        }
        return;
    }

    if (EPI == 2) {
        __half* C = (__half*)Cv + (ll)bz * sC;
        const float* rs = g_rsum + (size_t)bz * HW;
#pragma unroll
        for (int ti = 0; ti < 4; ti++) {
            int r0 = bm + wm + ti * 16 + lr;
            int r1 = r0 + 8;
            float inv0 = 1.f / rs[r0];
            float inv1 = 1.f / rs[r1];
#pragma unroll
            for (int tj = 0; tj < 4; tj++) {
                int col = bn + wn + tj * 8 + lc * 2;
                store_h2(C, (size_t)r0 * ldc + col, acc[ti][tj][0] * inv0, acc[ti][tj][1] * inv0);
                store_h2(C, (size_t)r1 * ldc + col, acc[ti][tj][2] * inv1, acc[ti][tj][3] * inv1);
            }
        }
        return;
    }

    // EPI == 0: fp32 out + row bias
    {
        float* C = (float*)Cv + (ll)bz * sC;
#pragma unroll
        for (int ti = 0; ti < 4; ti++) {
            int r0 = bm + wm + ti * 16 + lr;
            int r1 = r0 + 8;
            float bv0 = bias[r0];
            float bv1 = bias[r1];
#pragma unroll
            for (int tj = 0; tj < 4; tj++) {
                int col = bn + wn + tj * 8 + lc * 2;
                float2 o0 = { acc[ti][tj][0] + bv0, acc[ti][tj][1] + bv0 };
                float2 o1 = { acc[ti][tj][2] + bv1, acc[ti][tj][3] + bv1 };
                *(float2*)&C[(size_t)r0 * ldc + col] = o0;
                *(float2*)&C[(size_t)r1 * ldc + col] = o1;
            }
        }
    }
}

// ---------------- fused prep: transpose-convert inputs + convert weights ------
// grid (72, 16, 20): z<16 -> input slice (z<8: locx b=z; else glox b=z-8)
//                    z>=16 -> weight w=z-16 (flat convert); w==0 zeroes rsum
__global__ __launch_bounds__(256)
void prep_all(const float* __restrict__ Xl, const float* __restrict__ Xg,
              const float* __restrict__ W0, const float* __restrict__ W1,
              const float* __restrict__ W2, const float* __restrict__ W3)
{
    const int z = blockIdx.z;
    if (z >= 16) {
        const int w = z - 16;
        const float* W = (w == 0) ? W0 : (w == 1) ? W1 : (w == 2) ? W2 : W3;
        __half* R = (w == 0) ? g_wq : (w == 1) ? g_wk : (w == 2) ? g_wv : g_wo;
        const int i = (blockIdx.y * 72 + blockIdx.x) * 256 + threadIdx.x;
        if (i < HIDDEN * HIDDEN) R[i] = __float2half(W[i]);
        if (w == 0 && i < BATCH * HW) g_rsum[i] = 0.f;
        return;
    }
    __shared__ float tb[32][33];
    const int b = z & 7;
    const float* x = ((z < 8) ? Xl : Xg) + (size_t)b * HIDDEN * HW;
    __half* t = ((z < 8) ? g_lxT : g_gxT) + (size_t)b * HW * HIDDEN;
    const int n0 = blockIdx.x * 32, c0 = blockIdx.y * 32;
    const int tx = threadIdx.x & 31, ty = threadIdx.x >> 5;
#pragma unroll
    for (int j = 0; j < 4; j++)
        tb[ty + j * 8][tx] = x[(size_t)(c0 + ty + j * 8) * HW + n0 + tx];
    __syncthreads();
#pragma unroll
    for (int j = 0; j < 4; j++)
        t[(size_t)(n0 + ty + j * 8) * HIDDEN + c0 + tx] = __float2half(tb[tx][ty + j * 8]);
}

// ---------------- launch -----------------------------------------------------
extern "C" void kernel_launch(void* const* d_in, const int* in_sizes, int n_in,
                              void* d_out, int out_size)
{
    const float* locx = (const float*)d_in[0];
    const float* glox = (const float*)d_in[1];
    const float* Wq = (const float*)d_in[2];  const float* bq = (const float*)d_in[3];
    const float* Wk = (const float*)d_in[4];  const float* bk = (const float*)d_in[5];
    const float* Wv = (const float*)d_in[6];  const float* bv = (const float*)d_in[7];
    const float* Wo = (const float*)d_in[8];  const float* bo = (const float*)d_in[9];
    float* out = (float*)d_out;

    __half *q, *k, *v, *ctx, *S, *wo;
    { void* p; cudaGetSymbolAddress(&p, g_q);   q   = (__half*)p; }
    { void* p; cudaGetSymbolAddress(&p, g_k);   k   = (__half*)p; }
    { void* p; cudaGetSymbolAddress(&p, g_v);   v   = (__half*)p; }
    { void* p; cudaGetSymbolAddress(&p, g_ctx); ctx = (__half*)p; }
    { void* p; cudaGetSymbolAddress(&p, g_S);   S   = (__half*)p; }
    { void* p; cudaGetSymbolAddress(&p, g_wo);  wo  = (__half*)p; }

    cudaFuncSetAttribute(qkv_kernel, cudaFuncAttributeMaxDynamicSharedMemorySize, SMEMB);
    cudaFuncSetAttribute(gemm_h<0>, cudaFuncAttributeMaxDynamicSharedMemorySize, SMEMB);
    cudaFuncSetAttribute(gemm_h<1>, cudaFuncAttributeMaxDynamicSharedMemorySize, SMEMB);
    cudaFuncSetAttribute(gemm_h<2>, cudaFuncAttributeMaxDynamicSharedMemorySize, SMEMB);

    const ll sS = (ll)HW * HW;
    const float SCALE = 0.044194173824159216f;   // 1/sqrt(512)
    const int rowM = HW * 2;                     // 4608 B rows (K=2304 fp16)

    dim3 blk(256);

    // launch 0: fused prep (transpose+convert inputs, convert weights, zero rsum)
    prep_all<<<dim3(72, 16, 20), blk>>>(locx, glox, Wq, Wk, Wv, Wo);
    // launch 1: fused q/k/v projections
    qkv_kernel<<<dim3(4, 18, 24), blk, SMEMB>>>(bq, bk, bv);
    // launch 2: P[n,m] = exp(SCALE*q.k - ESHIFT) fp16, rsum += rows
    gemm_h<1><<<dim3(18, 18, 8), blk, SMEMB>>>(q, ROWC, SX * 2, k, ROWC, SX * 2,
                                               S, HW, sS, nullptr, HIDDEN, SCALE);
    // launch 3: ctx[n,co] = (P[n,:].v[co,:]) / rsum[n]  (fp16)
    gemm_h<2><<<dim3(4, 18, 8), blk, SMEMB>>>(S, rowM, sS * 2, v, rowM, SV * 2,
                                              ctx, HIDDEN, SX, nullptr, HW, 1.f);
    // launch 4: out[co,n] = wo[co,:].ctx[n,:] + bo[co]  (fp32)
    gemm_h<0><<<dim3(18, 4, 8), blk, SMEMB>>>(wo, ROWC, 0, ctx, ROWC, SX * 2,
                                              out, HW, SV, bo, HIDDEN, 1.f);
}

// round 17
// speedup vs baseline: 2.2182x; 1.0163x over previous
#include <cuda_runtime.h>
#include <cuda_fp16.h>
#include <math.h>
#include <stdint.h>

#define HIDDEN 512
#define BATCH  8
#define HW     2304   // 48*48

typedef long long ll;

// ---------------- scratch (static device globals; no allocs allowed) ----------
static __device__ __half g_lxT[(size_t)BATCH * HW * HIDDEN];  // locx^T fp16 [B][n][c]
static __device__ __half g_gxT[(size_t)BATCH * HW * HIDDEN];  // glox^T fp16
static __device__ __half g_q  [(size_t)BATCH * HW * HIDDEN];  // q  [B][n][c]
static __device__ __half g_k  [(size_t)BATCH * HW * HIDDEN];  // k  [B][m][c]
static __device__ __half g_v  [(size_t)BATCH * HIDDEN * HW];  // v  [B][c][m]
static __device__ __half g_ctx[(size_t)BATCH * HW * HIDDEN];  // ctx [B][n][c]
static __device__ __half g_S  [(size_t)BATCH * HW * HW];      // P (shifted exp) [B][n][m]
static __device__ float  g_rsum[(size_t)BATCH * HW];          // softmax row sums
static __device__ __half g_wq [HIDDEN * HIDDEN];
static __device__ __half g_wk [HIDDEN * HIDDEN];
static __device__ __half g_wv [HIDDEN * HIDDEN];
static __device__ __half g_wo [HIDDEN * HIDDEN];

// ---------------- helpers -----------------------------------------------------
__device__ __forceinline__ uint32_t smem_u32(const void* p) {
    uint32_t a;
    asm("{ .reg .u64 t; cvta.to.shared.u64 t, %1; cvt.u32.u64 %0, t; }" : "=r"(a) : "l"(p));
    return a;
}
__device__ __forceinline__ void cp16(uint32_t dst, const void* src) {
    asm volatile("cp.async.cg.shared.global [%0], [%1], 16;" :: "r"(dst), "l"(src));
}
__device__ __forceinline__ void ldsm4(uint32_t& r0, uint32_t& r1, uint32_t& r2, uint32_t& r3,
                                      uint32_t addr) {
    asm volatile("ldmatrix.sync.aligned.m8n8.x4.shared.b16 {%0,%1,%2,%3}, [%4];"
                 : "=r"(r0), "=r"(r1), "=r"(r2), "=r"(r3) : "r"(addr));
}
__device__ __forceinline__ void mma_f16(float& c0, float& c1, float& c2, float& c3,
                                        unsigned a0, unsigned a1, unsigned a2, unsigned a3,
                                        unsigned b0, unsigned b1)
{
    asm("mma.sync.aligned.m16n8k16.row.col.f32.f16.f16.f32 "
        "{%0,%1,%2,%3}, {%4,%5,%6,%7}, {%8,%9}, {%0,%1,%2,%3};"
        : "+f"(c0), "+f"(c1), "+f"(c2), "+f"(c3)
        : "r"(a0), "r"(a1), "r"(a2), "r"(a3), "r"(b0), "r"(b1));
}
// fp16-accumulator variant: {c0,c1} packed half2 (c0: row lr cols 2lc,2lc+1;
// c1: row lr+8 same cols)
__device__ __forceinline__ void mma_f16acc(unsigned& c0, unsigned& c1,
                                           unsigned a0, unsigned a1, unsigned a2, unsigned a3,
                                           unsigned b0, unsigned b1)
{
    asm("mma.sync.aligned.m16n8k16.row.col.f16.f16.f16.f16 "
        "{%0,%1}, {%2,%3,%4,%5}, {%6,%7}, {%0,%1};"
        : "+r"(c0), "+r"(c1)
        : "r"(a0), "r"(a1), "r"(a2), "r"(a3), "r"(b0), "r"(b1));
}
__device__ __forceinline__ void store_h2(__half* base, size_t idx, float a, float b) {
    __half2 h; h.x = __float2half(a); h.y = __float2half(b);
    *(__half2*)&base[idx] = h;
}

constexpr int TILE   = 128 * 128;       // 16 KB: 128 rows x 128 bytes (k64 fp16)
constexpr int STAGE  = 2 * TILE;        // 32 KB
constexpr int NSTAGE = 3;
constexpr int SMEMB  = NSTAGE * STAGE;  // 96 KB
constexpr float ESHIFT = 4.0f;          // softmax exp shift (cancels in normalize)
constexpr ll SX = (ll)HW * HIDDEN;      // [n][c] per-batch stride (elems)
constexpr ll SV = (ll)HIDDEN * HW;      // [c][m] per-batch stride (elems)
constexpr int ROWC = HIDDEN * 2;        // 1024 B rows (K=512 fp16)

// ---------------- shared frag setup -------------------------------------------
struct FragCtx {
    uint32_t dA[4], dB[4];
    const char *gA, *gB;
    uint32_t sb, aoff, boff;
    int achk, bchk, li;
};

__device__ __forceinline__ void frag_setup(FragCtx& cx, char* smem,
                                           const __half* A, int ldaB,
                                           const __half* B, int ldbB,
                                           int bm, int bn)
{
    cx.sb = smem_u32(smem);
    const int tid  = threadIdx.x;
    const int lane = tid & 31;
    const int warp = tid >> 5;
    const int row  = tid >> 1;
    const int half = tid & 1;
    cx.gA = (const char*)A + (size_t)(bm + row) * ldaB + half * 64;
    cx.gB = (const char*)B + (size_t)(bn + row) * ldbB + half * 64;
#pragma unroll
    for (int j = 0; j < 4; j++) {
        int c = half * 4 + j;
        uint32_t off = row * 128 + (((c ^ (row & 7))) << 4);
        cx.dA[j] = cx.sb + off;
        cx.dB[j] = cx.sb + TILE + off;
    }
    const int mi = lane >> 3;
    cx.li = lane & 7;
    const int wm = (warp & 1) * 64;
    const int wn = (warp >> 1) * 32;
    cx.aoff = (uint32_t)(wm + (mi & 1) * 8 + cx.li) * 128;
    cx.achk = mi >> 1;
    cx.boff = TILE + (uint32_t)(wn + (mi >> 1) * 8 + cx.li) * 128;
    cx.bchk = mi & 1;
}

__device__ __forceinline__ void pipe_issue(FragCtx& cx, int s, int t) {
    uint32_t st = s * STAGE;
    const char* pa = cx.gA + (size_t)t * 128;
    const char* pb = cx.gB + (size_t)t * 128;
#pragma unroll
    for (int j = 0; j < 4; j++) cp16(cx.dA[j] + st, pa + j * 16);
#pragma unroll
    for (int j = 0; j < 4; j++) cp16(cx.dB[j] + st, pb + j * 16);
    asm volatile("cp.async.commit_group;");
}

// ---------------- fp32-acc core mainloop --------------------------------------
__device__ __forceinline__ void gemm_core(FragCtx& cx, float acc[4][4][4], int nT)
{
#pragma unroll
    for (int i = 0; i < 4; i++)
#pragma unroll
        for (int j = 0; j < 4; j++)
#pragma unroll
            for (int r = 0; r < 4; r++) acc[i][j][r] = 0.f;

    pipe_issue(cx, 0, 0);
    pipe_issue(cx, 1, 1);

    int stage = 0;
    for (int t = 0; t < nT; t++) {
        if (t < nT - 1) asm volatile("cp.async.wait_group 1;");
        else            asm volatile("cp.async.wait_group 0;");
        __syncthreads();

        if (t + 2 < nT) {
            int ps = stage + 2; if (ps >= NSTAGE) ps -= NSTAGE;
            pipe_issue(cx, ps, t + 2);
        }

        const uint32_t st = cx.sb + stage * STAGE;
#pragma unroll
        for (int kb = 0; kb < 4; kb++) {
            const int c0 = kb * 2;
            uint32_t af[4][4];
            uint32_t bf[4][2];
#pragma unroll
            for (int tp = 0; tp < 2; tp++)
                ldsm4(bf[2 * tp][0], bf[2 * tp][1], bf[2 * tp + 1][0], bf[2 * tp + 1][1],
                      st + tp * 2048 + cx.boff + (((c0 + cx.bchk) ^ cx.li) << 4));
#pragma unroll
            for (int ti = 0; ti < 4; ti++)
                ldsm4(af[ti][0], af[ti][1], af[ti][2], af[ti][3],
                      st + ti * 2048 + cx.aoff + (((c0 + cx.achk) ^ cx.li) << 4));
#pragma unroll
            for (int ti = 0; ti < 4; ti++)
#pragma unroll
                for (int tj = 0; tj < 4; tj++)
                    mma_f16(acc[ti][tj][0], acc[ti][tj][1], acc[ti][tj][2], acc[ti][tj][3],
                            af[ti][0], af[ti][1], af[ti][2], af[ti][3],
                            bf[tj][0], bf[tj][1]);
        }
        if (++stage == NSTAGE) stage = 0;
    }
}

// ---------------- fp16-acc core mainloop (score), TWO chains ------------------
// Chunk t accumulates into chain (t&1); chains summed in fp32 at epilogue.
// Halves each accumulation chain length -> fp16 rounding error sd x 1/sqrt(2).
// Register cost: 2 x 32 = 64 acc regs == the fp32-acc budget.
__device__ __forceinline__ void gemm_core_h2(FragCtx& cx, unsigned acc[2][4][4][2], int nT)
{
#pragma unroll
    for (int p = 0; p < 2; p++)
#pragma unroll
        for (int i = 0; i < 4; i++)
#pragma unroll
            for (int j = 0; j < 4; j++) { acc[p][i][j][0] = 0u; acc[p][i][j][1] = 0u; }

    pipe_issue(cx, 0, 0);
    pipe_issue(cx, 1, 1);

    int stage = 0;
    for (int t = 0; t < nT; t++) {
        if (t < nT - 1) asm volatile("cp.async.wait_group 1;");
        else            asm volatile("cp.async.wait_group 0;");
        __syncthreads();

        if (t + 2 < nT) {
            int ps = stage + 2; if (ps >= NSTAGE) ps -= NSTAGE;
            pipe_issue(cx, ps, t + 2);
        }

        const uint32_t st = cx.sb + stage * STAGE;
        const int ch = t & 1;
#pragma unroll
        for (int kb = 0; kb < 4; kb++) {
            const int c0 = kb * 2;
            uint32_t af[4][4];
            uint32_t bf[4][2];
#pragma unroll
            for (int tp = 0; tp < 2; tp++)
                ldsm4(bf[2 * tp][0], bf[2 * tp][1], bf[2 * tp + 1][0], bf[2 * tp + 1][1],
                      st + tp * 2048 + cx.boff + (((c0 + cx.bchk) ^ cx.li) << 4));
#pragma unroll
            for (int ti = 0; ti < 4; ti++)
                ldsm4(af[ti][0], af[ti][1], af[ti][2], af[ti][3],
                      st + ti * 2048 + cx.aoff + (((c0 + cx.achk) ^ cx.li) << 4));
#pragma unroll
            for (int ti = 0; ti < 4; ti++)
#pragma unroll
                for (int tj = 0; tj < 4; tj++)
                    mma_f16acc(acc[ch][ti][tj][0], acc[ch][ti][tj][1],
                               af[ti][0], af[ti][1], af[ti][2], af[ti][3],
                               bf[tj][0], bf[tj][1]);
        }
        if (++stage == NSTAGE) stage = 0;
    }
}

// ---------------- fused Q/K/V projection kernel -------------------------------
// grid (4, 18, 24): z = op*8 + b; op 0:q 1:k 2:v. All K = 512.
__global__ __launch_bounds__(256, 2)
void qkv_kernel(const float* __restrict__ bq, const float* __restrict__ bk,
                const float* __restrict__ bv)
{
    extern __shared__ __align__(1024) char smem[];
    const int z = blockIdx.z;
    const int op = z >> 3;
    const int b  = z & 7;

    const __half* A;
    const __half* B;
    __half* C;
    const float* bias;
    int bm, bn, ldc, bmode;
    if (op == 0) {
        A = g_lxT + (size_t)b * SX; B = g_wq; C = g_q + (size_t)b * SX;
        bias = bq; bm = blockIdx.y * 128; bn = blockIdx.x * 128; ldc = HIDDEN; bmode = 2;
    } else if (op == 1) {
        A = g_gxT + (size_t)b * SX; B = g_wk; C = g_k + (size_t)b * SX;
        bias = bk; bm = blockIdx.y * 128; bn = blockIdx.x * 128; ldc = HIDDEN; bmode = 2;
    } else {
        A = g_wv; B = g_gxT + (size_t)b * SX; C = g_v + (size_t)b * SV;
        bias = bv; bm = blockIdx.x * 128; bn = blockIdx.y * 128; ldc = HW; bmode = 1;
    }

    FragCtx cx;
    frag_setup(cx, smem, A, ROWC, B, ROWC, bm, bn);
    float acc[4][4][4];
    gemm_core(cx, acc, HIDDEN / 64);

    const int warp = threadIdx.x >> 5;
    const int lane = threadIdx.x & 31;
    const int lr = lane >> 2, lc = lane & 3;
    const int wm = (warp & 1) * 64, wn = (warp >> 1) * 32;
#pragma unroll
    for (int ti = 0; ti < 4; ti++) {
        int r0 = bm + wm + ti * 16 + lr;
        int r1 = r0 + 8;
        float bv0 = (bmode == 1) ? bias[r0] : 0.f;
        float bv1 = (bmode == 1) ? bias[r1] : 0.f;
#pragma unroll
        for (int tj = 0; tj < 4; tj++) {
            int col = bn + wn + tj * 8 + lc * 2;
            float c0 = acc[ti][tj][0], c1 = acc[ti][tj][1];
            float c2 = acc[ti][tj][2], c3 = acc[ti][tj][3];
            if (bmode == 1) { c0 += bv0; c1 += bv0; c2 += bv1; c3 += bv1; }
            else            { float b0 = bias[col], b1 = bias[col + 1];
                              c0 += b0; c1 += b1; c2 += b0; c3 += b1; }
            store_h2(C, (size_t)r0 * ldc + col, c0, c1);
            store_h2(C, (size_t)r1 * ldc + col, c2, c3);
        }
    }
}

// ---------------- score kernel (2-chain fp16 accumulators) --------------------
// P[n,m] = exp(SCALE*(chain0+chain1) - ESHIFT) fp16 + atomic fp32 row sums.
__global__ __launch_bounds__(256, 2)
void score_kernel(const __half* __restrict__ q, const __half* __restrict__ k,
                  __half* __restrict__ S, float alpha)
{
    extern __shared__ __align__(1024) char smem[];
    const int bz = blockIdx.z;
    const int bm = blockIdx.y * 128;
    const int bn = blockIdx.x * 128;

    FragCtx cx;
    frag_setup(cx, smem, q + (size_t)bz * SX, ROWC, k + (size_t)bz * SX, ROWC, bm, bn);
    unsigned acc[2][4][4][2];
    gemm_core_h2(cx, acc, HIDDEN / 64);

    const int warp = threadIdx.x >> 5;
    const int lane = threadIdx.x & 31;
    const int lr = lane >> 2, lc = lane & 3;
    const int wm = (warp & 1) * 64, wn = (warp >> 1) * 32;

    __half* C = S + (size_t)bz * HW * HW;
    float* rs = g_rsum + (size_t)bz * HW;
#pragma unroll
    for (int ti = 0; ti < 4; ti++) {
        int r0 = bm + wm + ti * 16 + lr;
        int r1 = r0 + 8;
        float s0 = 0.f, s1 = 0.f;
#pragma unroll
        for (int tj = 0; tj < 4; tj++) {
            int col = bn + wn + tj * 8 + lc * 2;
            float2 e0a = __half22float2(*(__half2*)&acc[0][ti][tj][0]);
            float2 e1a = __half22float2(*(__half2*)&acc[1][ti][tj][0]);
            float2 e0b = __half22float2(*(__half2*)&acc[0][ti][tj][1]);
            float2 e1b = __half22float2(*(__half2*)&acc[1][ti][tj][1]);
            float v00 = e0a.x + e1a.x;   // row lr,   col 2lc
            float v01 = e0a.y + e1a.y;   // row lr,   col 2lc+1
            float v10 = e0b.x + e1b.x;   // row lr+8, col 2lc
            float v11 = e0b.y + e1b.y;   // row lr+8, col 2lc+1
            float p0 = __expf(alpha * v00 - ESHIFT);
            float p1 = __expf(alpha * v01 - ESHIFT);
            float p2 = __expf(alpha * v10 - ESHIFT);
            float p3 = __expf(alpha * v11 - ESHIFT);
            s0 += p0 + p1;
            s1 += p2 + p3;
            store_h2(C, (size_t)r0 * HW + col, p0, p1);
            store_h2(C, (size_t)r1 * HW + col, p2, p3);
        }
        s0 += __shfl_xor_sync(0xFFFFFFFFu, s0, 1);
        s0 += __shfl_xor_sync(0xFFFFFFFFu, s0, 2);
        s1 += __shfl_xor_sync(0xFFFFFFFFu, s1, 1);
        s1 += __shfl_xor_sync(0xFFFFFFFFu, s1, 2);
        if (lc == 0) {
            atomicAdd(&rs[r0], s0);
            atomicAdd(&rs[r1], s1);
        }
    }
}

// ---------------- PV / out kernels (fp32 acc) ---------------------------------
// EPI 2: PV (A=P, B=v, K=2304): ctx = acc / rsum[row], fp16
// EPI 0: out (A=wo, B=ctx, K=512): fp32 + row bias
template<int EPI>
__global__ __launch_bounds__(256, 2)
void gemm_h(const __half* __restrict__ A, int ldaB, ll sAB,
            const __half* __restrict__ B, int ldbB, ll sBB,
            void* __restrict__ Cv, int ldc, ll sC,
            const float* __restrict__ bias, int K)
{
    extern __shared__ __align__(1024) char smem[];
    const int bz = blockIdx.z;
    const int bm = blockIdx.y * 128;
    const int bn = blockIdx.x * 128;

    FragCtx cx;
    frag_setup(cx, smem,
               (const __half*)((const char*)A + (ll)bz * sAB), ldaB,
               (const __half*)((const char*)B + (ll)bz * sBB), ldbB,
               bm, bn);
    float acc[4][4][4];
    gemm_core(cx, acc, K / 64);

    const int warp = threadIdx.x >> 5;
    const int lane = threadIdx.x & 31;
    const int lr = lane >> 2, lc = lane & 3;
    const int wm = (warp & 1) * 64, wn = (warp >> 1) * 32;

    if (EPI == 2) {
        __half* C = (__half*)Cv + (ll)bz * sC;
        const float* rs = g_rsum + (size_t)bz * HW;
#pragma unroll
        for (int ti = 0; ti < 4; ti++) {
            int r0 = bm + wm + ti * 16 + lr;
            int r1 = r0 + 8;
            float inv0 = 1.f / rs[r0];
            float inv1 = 1.f / rs[r1];
#pragma unroll
            for (int tj = 0; tj < 4; tj++) {
                int col = bn + wn + tj * 8 + lc * 2;
                store_h2(C, (size_t)r0 * ldc + col, acc[ti][tj][0] * inv0, acc[ti][tj][1] * inv0);
                store_h2(C, (size_t)r1 * ldc + col, acc[ti][tj][2] * inv1, acc[ti][tj][3] * inv1);
            }
        }
        return;
    }

    // EPI == 0: fp32 out + row bias
    {
        float* C = (float*)Cv + (ll)bz * sC;
#pragma unroll
        for (int ti = 0; ti < 4; ti++) {
            int r0 = bm + wm + ti * 16 + lr;
            int r1 = r0 + 8;
            float bv0 = bias[r0];
            float bv1 = bias[r1];
#pragma unroll
            for (int tj = 0; tj < 4; tj++) {
                int col = bn + wn + tj * 8 + lc * 2;
                float2 o0 = { acc[ti][tj][0] + bv0, acc[ti][tj][1] + bv0 };
                float2 o1 = { acc[ti][tj][2] + bv1, acc[ti][tj][3] + bv1 };
                *(float2*)&C[(size_t)r0 * ldc + col] = o0;
                *(float2*)&C[(size_t)r1 * ldc + col] = o1;
            }
        }
    }
}

// ---------------- fused prep: transpose-convert inputs + convert weights ------
// grid (72, 16, 20): z<16 -> input slice (z<8: locx b=z; else glox b=z-8)
//                    z>=16 -> weight w=z-16 (flat convert); w==0 zeroes rsum
__global__ __launch_bounds__(256)
void prep_all(const float* __restrict__ Xl, const float* __restrict__ Xg,
              const float* __restrict__ W0, const float* __restrict__ W1,
              const float* __restrict__ W2, const float* __restrict__ W3)
{
    const int z = blockIdx.z;
    if (z >= 16) {
        const int w = z - 16;
        const float* W = (w == 0) ? W0 : (w == 1) ? W1 : (w == 2) ? W2 : W3;
        __half* R = (w == 0) ? g_wq : (w == 1) ? g_wk : (w == 2) ? g_wv : g_wo;
        const int i = (blockIdx.y * 72 + blockIdx.x) * 256 + threadIdx.x;
        if (i < HIDDEN * HIDDEN) R[i] = __float2half(W[i]);
        if (w == 0 && i < BATCH * HW) g_rsum[i] = 0.f;
        return;
    }
    __shared__ float tb[32][33];
    const int b = z & 7;
    const float* x = ((z < 8) ? Xl : Xg) + (size_t)b * HIDDEN * HW;
    __half* t = ((z < 8) ? g_lxT : g_gxT) + (size_t)b * HW * HIDDEN;
    const int n0 = blockIdx.x * 32, c0 = blockIdx.y * 32;
    const int tx = threadIdx.x & 31, ty = threadIdx.x >> 5;
#pragma unroll
    for (int j = 0; j < 4; j++)
        tb[ty + j * 8][tx] = x[(size_t)(c0 + ty + j * 8) * HW + n0 + tx];
    __syncthreads();
#pragma unroll
    for (int j = 0; j < 4; j++)
        t[(size_t)(n0 + ty + j * 8) * HIDDEN + c0 + tx] = __float2half(tb[tx][ty + j * 8]);
}

// ---------------- launch -----------------------------------------------------
extern "C" void kernel_launch(void* const* d_in, const int* in_sizes, int n_in,
                              void* d_out, int out_size)
{
    const float* locx = (const float*)d_in[0];
    const float* glox = (const float*)d_in[1];
    const float* Wq = (const float*)d_in[2];  const float* bq = (const float*)d_in[3];
    const float* Wk = (const float*)d_in[4];  const float* bk = (const float*)d_in[5];
    const float* Wv = (const float*)d_in[6];  const float* bv = (const float*)d_in[7];
    const float* Wo = (const float*)d_in[8];  const float* bo = (const float*)d_in[9];
    float* out = (float*)d_out;

    __half *q, *k, *v, *ctx, *S, *wo;
    { void* p; cudaGetSymbolAddress(&p, g_q);   q   = (__half*)p; }
    { void* p; cudaGetSymbolAddress(&p, g_k);   k   = (__half*)p; }
    { void* p; cudaGetSymbolAddress(&p, g_v);   v   = (__half*)p; }
    { void* p; cudaGetSymbolAddress(&p, g_ctx); ctx = (__half*)p; }
    { void* p; cudaGetSymbolAddress(&p, g_S);   S   = (__half*)p; }
    { void* p; cudaGetSymbolAddress(&p, g_wo);  wo  = (__half*)p; }

    cudaFuncSetAttribute(qkv_kernel,   cudaFuncAttributeMaxDynamicSharedMemorySize, SMEMB);
    cudaFuncSetAttribute(score_kernel, cudaFuncAttributeMaxDynamicSharedMemorySize, SMEMB);
    cudaFuncSetAttribute(gemm_h<0>, cudaFuncAttributeMaxDynamicSharedMemorySize, SMEMB);
    cudaFuncSetAttribute(gemm_h<2>, cudaFuncAttributeMaxDynamicSharedMemorySize, SMEMB);

    const ll sS = (ll)HW * HW;
    const float SCALE = 0.044194173824159216f;   // 1/sqrt(512)
    const int rowM = HW * 2;                     // 4608 B rows (K=2304 fp16)

    dim3 blk(256);

    // launch 0: fused prep (transpose+convert inputs, convert weights, zero rsum)
    prep_all<<<dim3(72, 16, 20), blk>>>(locx, glox, Wq, Wk, Wv, Wo);
    // launch 1: fused q/k/v projections
    qkv_kernel<<<dim3(4, 18, 24), blk, SMEMB>>>(bq, bk, bv);
    // launch 2: P[n,m] = exp(SCALE*q.k - ESHIFT), 2-chain fp16 acc, rsum += rows
    score_kernel<<<dim3(18, 18, 8), blk, SMEMB>>>(q, k, S, SCALE);
    // launch 3: ctx[n,co] = (P[n,:].v[co,:]) / rsum[n]  (fp16, fp32 acc)
    gemm_h<2><<<dim3(4, 18, 8), blk, SMEMB>>>(S, rowM, sS * 2, v, rowM, SV * 2,
                                              ctx, HIDDEN, SX, nullptr, HW);
    // launch 4: out[co,n] = wo[co,:].ctx[n,:] + bo[co]  (fp32)
    gemm_h<0><<<dim3(18, 4, 8), blk, SMEMB>>>(wo, ROWC, 0, ctx, ROWC, SX * 2,
                                              out, HW, SV, bo, HIDDEN);
}